// round 8
// baseline (speedup 1.0000x reference)
#include <cuda_runtime.h>
#include <cuda_bf16.h>
#include <math.h>
#include <stdint.h>

// ---------------- model dims ----------------
#define Bz   2
#define Ss   1024
#define Tt   (Bz*Ss)        // 2048 tokens
#define Dd   1024
#define Hh   16
#define KVh  4
#define HDd  64
#define Ll   4
#define Ee   8
#define Ff   1024
#define Vv   32000

// ---------------- scratch (device globals; no allocation) ----------------
__device__ float g_x[Tt*Dd];
__device__ float g_h[Tt*Dd];
__device__ float g_q[Tt*Hh*HDd];
__device__ float g_k[Tt*KVh*HDd];
__device__ float g_v[Tt*KVh*HDd];
__device__ float g_o[Tt*Hh*HDd];
__device__ float g_scores[(size_t)Bz*Hh*Ss*Ss];   // 134 MB
__device__ float g_gbuf[Tt*Ff];
__device__ float g_ubuf[Tt*Ff];
__device__ int   g_eidx[Ee*Tt];
__device__ float g_egate[Ee*Tt];
__device__ int   g_ecnt[Ee];

// ---------------- helpers ----------------
__device__ __forceinline__ float tf32r(float x) {
    uint32_t u;
    asm("cvt.rna.tf32.f32 %0, %1;" : "=r"(u) : "f"(x));
    return __uint_as_float(u);
}

__device__ __forceinline__ void mma8(float* c, const uint32_t* a, const uint32_t* b) {
    asm volatile("mma.sync.aligned.m16n8k8.row.col.f32.tf32.tf32.f32 "
                 "{%0,%1,%2,%3}, {%4,%5,%6,%7}, {%8,%9}, {%0,%1,%2,%3};"
                 : "+f"(c[0]), "+f"(c[1]), "+f"(c[2]), "+f"(c[3])
                 : "r"(a[0]), "r"(a[1]), "r"(a[2]), "r"(a[3]),
                   "r"(b[0]), "r"(b[1]));
}

__device__ __forceinline__ float blockReduceSum256(float v) {
    __shared__ float sh[32];
    int lane = threadIdx.x & 31, wid = threadIdx.x >> 5;
    #pragma unroll
    for (int o = 16; o; o >>= 1) v += __shfl_xor_sync(0xffffffffu, v, o);
    if (lane == 0) sh[wid] = v;
    __syncthreads();
    int nw = (blockDim.x + 31) >> 5;
    float r = (threadIdx.x < nw) ? sh[threadIdx.x] : 0.f;
    if (wid == 0) {
        #pragma unroll
        for (int o = 16; o; o >>= 1) r += __shfl_xor_sync(0xffffffffu, r, o);
        if (lane == 0) sh[0] = r;
    }
    __syncthreads();
    float out = sh[0];
    __syncthreads();
    return out;
}

__device__ __forceinline__ float blockReduceMax256(float v) {
    __shared__ float sh[32];
    int lane = threadIdx.x & 31, wid = threadIdx.x >> 5;
    #pragma unroll
    for (int o = 16; o; o >>= 1) v = fmaxf(v, __shfl_xor_sync(0xffffffffu, v, o));
    if (lane == 0) sh[wid] = v;
    __syncthreads();
    int nw = (blockDim.x + 31) >> 5;
    float r = (threadIdx.x < nw) ? sh[threadIdx.x] : -INFINITY;
    if (wid == 0) {
        #pragma unroll
        for (int o = 16; o; o >>= 1) r = fmaxf(r, __shfl_xor_sync(0xffffffffu, r, o));
        if (lane == 0) sh[0] = r;
    }
    __syncthreads();
    float out = sh[0];
    __syncthreads();
    return out;
}

// ---------------- elementwise kernels ----------------
__global__ void embed_k(const int* __restrict__ tok, const float* __restrict__ emb,
                        float* __restrict__ x) {
    int i = blockIdx.x * 256 + threadIdx.x;
    int t = i / Dd, d = i % Dd;
    x[i] = emb[(long)tok[t] * Dd + d];
}

__global__ void rmsnorm_k(const float* __restrict__ x, const float* __restrict__ w,
                          float* __restrict__ out) {
    int row = blockIdx.x;
    const float* xr = x + (long)row * Dd;
    float* orow = out + (long)row * Dd;
    float ss = 0.f;
    #pragma unroll
    for (int i = 0; i < 4; i++) {
        float v = xr[threadIdx.x + i * 256];
        ss += v * v;
    }
    float tot = blockReduceSum256(ss);
    float scale = rsqrtf(tot / (float)Dd + 1e-6f);
    #pragma unroll
    for (int i = 0; i < 4; i++) {
        int d = threadIdx.x + i * 256;
        orow[d] = xr[d] * scale * w[d];
    }
}

// per-head RMSNorm + RoPE, in place. block = 64 threads = one (token, head)
__global__ void qknorm_rope_k(float* __restrict__ qk, const float* __restrict__ nw,
                              const int* __restrict__ pos, int nHeads, int ld) {
    int bid = blockIdx.x;
    int t = bid / nHeads, hh = bid % nHeads;
    float* v = qk + (long)t * ld + hh * HDd;
    int d = threadIdx.x;
    float x = v[d];
    float ss = x * x;
    #pragma unroll
    for (int o = 16; o; o >>= 1) ss += __shfl_xor_sync(0xffffffffu, ss, o);
    __shared__ float s2[2];
    if ((d & 31) == 0) s2[d >> 5] = ss;
    __syncthreads();
    float tot = s2[0] + s2[1];
    float scale = rsqrtf(tot / 64.f + 1e-6f);
    float xn = x * scale * nw[d];
    __shared__ float sh[64];
    sh[d] = xn;
    __syncthreads();
    int p = pos[t];
    int fi = d & 31;
    float inv = powf(1e6f, -(float)fi / 32.f);
    float ang = (float)p * inv;
    float c = cosf(ang), s = sinf(ang);
    float other = (d < 32) ? sh[d + 32] : sh[d - 32];
    float rot = (d < 32) ? -other : other;
    v[d] = xn * c + rot * s;
}

// causal softmax over scores rows; zero-fills j>q
__global__ void softmax_k(float* __restrict__ scores) {
    long row = blockIdx.x;                 // B*H*S rows
    int q = (int)(row % Ss);
    float* p = scores + row * Ss;
    int valid = q + 1;
    float mx = -INFINITY;
    for (int j = threadIdx.x; j < valid; j += 256) mx = fmaxf(mx, p[j]);
    mx = blockReduceMax256(mx);
    float sum = 0.f;
    for (int j = threadIdx.x; j < valid; j += 256) {
        float e = expf(p[j] - mx);
        p[j] = e;
        sum += e;
    }
    sum = blockReduceSum256(sum);
    float inv = 1.f / sum;
    for (int j = threadIdx.x; j < valid; j += 256) p[j] *= inv;
    for (int j = valid + threadIdx.x; j < Ss; j += 256) p[j] = 0.f;
}

__global__ void zero_cnt_k(int* c) { if (threadIdx.x < Ee) c[threadIdx.x] = 0; }

// router: logits = h @ rw [D,E]; top-2; normalize among top-2; fill expert lists
__global__ void router_k(const float* __restrict__ h, const float* __restrict__ rw,
                         int* __restrict__ ecnt, int* __restrict__ eidx,
                         float* __restrict__ egate) {
    int t = blockIdx.x;
    int lane = threadIdx.x & 31, w = threadIdx.x >> 5;   // warp per expert
    const float* hr = h + (long)t * Dd;
    float s = 0.f;
    for (int d = lane; d < Dd; d += 32) s += hr[d] * rw[(long)d * Ee + w];
    #pragma unroll
    for (int o = 16; o; o >>= 1) s += __shfl_xor_sync(0xffffffffu, s, o);
    __shared__ float lg[Ee];
    if (lane == 0) lg[w] = s;
    __syncthreads();
    if (threadIdx.x == 0) {
        int a = 0;
        #pragma unroll
        for (int i = 1; i < Ee; i++) if (lg[i] > lg[a]) a = i;
        int b = (a == 0) ? 1 : 0;
        #pragma unroll
        for (int i = 0; i < Ee; i++) if (i != a && lg[i] > lg[b]) b = i;
        float wa = 1.f / (1.f + expf(lg[b] - lg[a]));
        float wb = 1.f - wa;
        int pa = atomicAdd(&ecnt[a], 1);
        eidx[a * Tt + pa] = t; egate[a * Tt + pa] = wa;
        int pb = atomicAdd(&ecnt[b], 1);
        eidx[b * Tt + pb] = t; egate[b * Tt + pb] = wb;
    }
}

__global__ void silu_mul_k(float* __restrict__ g, const float* __restrict__ u,
                           const int* __restrict__ cnt) {
    long n = (long)(*cnt) * Ff;
    long i = (long)blockIdx.x * 256 + threadIdx.x;
    if (i >= n) return;
    float x = g[i];
    g[i] = (x / (1.f + expf(-x))) * u[i];
}

// ---------------- 3xTF32 tensor-core tiled GEMM (128x128 tile) ----------------
// C[M,N] = alpha * A(MxK) * op(B) (+C if addC); op(B)=B (KxN) or B^T (B is NxK).
// Tile 128x128x16, 256 threads = 8 warps (2x4), warp tile 64x32 via m16n8k8 tf32.
// Raw fp32 staged in smem; hi/lo tf32 split happens at fragment-load time.
// 3xTF32: a*b ~= ahi*bhi + ahi*blo + alo*bhi accumulated in fp32.
// Assumes K % 16 == 0 and N % 8 == 0 (true for every GEMM in this model).
// GATHER: A row m -> A[idx[m]]. SCATTER: C[idx[m]] += gate[m]*val (rows unique).
template<bool TRANSB, bool GATHER, bool SCATTER>
__global__ void __launch_bounds__(256, 1) gemm_k(
    const float* __restrict__ A, const float* __restrict__ B, float* __restrict__ C,
    int M, int N, int K, int lda, int ldb, int ldc,
    float alpha, int addC, int causal,
    const int* __restrict__ idx, const float* __restrict__ gate,
    const int* __restrict__ Mdev,
    long sAb, long sAh, long sBb, long sBh, long sCb, long sCh,
    int nH, int hDiv)
{
    if (Mdev) M = *Mdev;
    int m0 = blockIdx.y * 128, n0 = blockIdx.x * 128;
    if (m0 >= M) return;
    if (causal && n0 >= m0 + 128) return;
    {
        int z = blockIdx.z;
        int b = z / nH, h = z % nH;
        A += (long)b * sAb + (long)h * sAh;
        B += (long)b * sBb + (long)(h / hDiv) * sBh;
        C += (long)b * sCb + (long)h * sCh;
    }

    __shared__ float As[2][128][20];   // stride 20: conflict-free frag reads
    __shared__ float Bs[2][16][136];   // stride 136 (=8 mod 32): conflict-free

    int tid = threadIdx.x;
    int lane = tid & 31, warp = tid >> 5;
    int wm = (warp >> 2) * 64, wn = (warp & 3) * 32;
    int qrow = lane >> 2, qk = lane & 3;

    // A global-load geometry: 2 rows x float4 per thread (rows r, r+64)
    int ar_r = tid >> 2;               // 0..63
    int ac4 = (tid & 3) * 4;
    int gr0 = m0 + ar_r, gr1 = gr0 + 64;
    bool av0 = gr0 < M, av1 = gr1 < M;
    long arow0 = 0, arow1 = 0;
    if (av0) arow0 = (long)(GATHER ? idx[gr0] : gr0) * lda;
    if (av1) arow1 = (long)(GATHER ? idx[gr1] : gr1) * lda;

    // B global-load geometry
    int bnr, bc4;
    bool bv0, bv1;
    if (TRANSB) {
        bnr = tid >> 2; bc4 = (tid & 3) * 4;       // n-rows bnr, bnr+64; k-col bc4
        bv0 = (n0 + bnr) < N; bv1 = (n0 + bnr + 64) < N;
    } else {
        bnr = tid >> 5; bc4 = (tid & 31) * 4;      // k-rows bnr, bnr+8; n-col bc4
        bv0 = bv1 = (n0 + bc4) < N;
    }

    float4 pa0, pa1, pb0, pb1;
    const float4 z4 = make_float4(0.f, 0.f, 0.f, 0.f);

    float acc[4][4][4];
    #pragma unroll
    for (int mt = 0; mt < 4; mt++)
        #pragma unroll
        for (int nt = 0; nt < 4; nt++)
            #pragma unroll
            for (int i = 0; i < 4; i++) acc[mt][nt][i] = 0.f;

    auto LDG = [&](int k0) {
        pa0 = av0 ? *(const float4*)(A + arow0 + k0 + ac4) : z4;
        pa1 = av1 ? *(const float4*)(A + arow1 + k0 + ac4) : z4;
        if (TRANSB) {
            pb0 = bv0 ? *(const float4*)(B + (long)(n0 + bnr) * ldb + k0 + bc4) : z4;
            pb1 = bv1 ? *(const float4*)(B + (long)(n0 + bnr + 64) * ldb + k0 + bc4) : z4;
        } else {
            pb0 = bv0 ? *(const float4*)(B + (long)(k0 + bnr) * ldb + n0 + bc4) : z4;
            pb1 = bv1 ? *(const float4*)(B + (long)(k0 + bnr + 8) * ldb + n0 + bc4) : z4;
        }
    };

    auto STS = [&](int buf) {
        *(float4*)&As[buf][ar_r][ac4] = pa0;
        *(float4*)&As[buf][ar_r + 64][ac4] = pa1;
        if (TRANSB) {
            Bs[buf][bc4 + 0][bnr] = pb0.x;
            Bs[buf][bc4 + 1][bnr] = pb0.y;
            Bs[buf][bc4 + 2][bnr] = pb0.z;
            Bs[buf][bc4 + 3][bnr] = pb0.w;
            Bs[buf][bc4 + 0][bnr + 64] = pb1.x;
            Bs[buf][bc4 + 1][bnr + 64] = pb1.y;
            Bs[buf][bc4 + 2][bnr + 64] = pb1.z;
            Bs[buf][bc4 + 3][bnr + 64] = pb1.w;
        } else {
            *(float4*)&Bs[buf][bnr][bc4] = pb0;
            *(float4*)&Bs[buf][bnr + 8][bc4] = pb1;
        }
    };

    auto split = [&](float v, uint32_t& hi, uint32_t& lo) {
        float h = tf32r(v);
        hi = __float_as_uint(h);
        lo = __float_as_uint(tf32r(v - h));
    };

    auto COMPUTE = [&](int buf) {
        #pragma unroll
        for (int ks = 0; ks < 2; ks++) {
            int kk = ks * 8 + qk;
            uint32_t afh[4][4], afl[4][4];
            #pragma unroll
            for (int mt = 0; mt < 4; mt++) {
                int r = wm + mt * 16 + qrow;
                split(As[buf][r][kk],          afh[mt][0], afl[mt][0]);
                split(As[buf][r + 8][kk],      afh[mt][1], afl[mt][1]);
                split(As[buf][r][kk + 4],      afh[mt][2], afl[mt][2]);
                split(As[buf][r + 8][kk + 4],  afh[mt][3], afl[mt][3]);
            }
            uint32_t bfh[4][2], bfl[4][2];
            #pragma unroll
            for (int nt = 0; nt < 4; nt++) {
                int cn = wn + nt * 8 + qrow;
                split(Bs[buf][kk][cn],      bfh[nt][0], bfl[nt][0]);
                split(Bs[buf][kk + 4][cn],  bfh[nt][1], bfl[nt][1]);
            }
            #pragma unroll
            for (int mt = 0; mt < 4; mt++)
                #pragma unroll
                for (int nt = 0; nt < 4; nt++) {
                    mma8(acc[mt][nt], afh[mt], bfl[nt]);   // hi*lo
                    mma8(acc[mt][nt], afl[mt], bfh[nt]);   // lo*hi
                    mma8(acc[mt][nt], afh[mt], bfh[nt]);   // hi*hi
                }
        }
    };

    int KT = K >> 4;
    LDG(0);
    STS(0);
    __syncthreads();
    for (int kt = 0; kt < KT; kt++) {
        int cur = kt & 1;
        bool more = (kt + 1) < KT;
        if (more) LDG((kt + 1) * 16);
        COMPUTE(cur);
        if (more) {
            __syncthreads();
            STS(cur ^ 1);
            __syncthreads();
        }
    }

    // ---- epilogue ----
    #pragma unroll
    for (int mt = 0; mt < 4; mt++) {
        #pragma unroll
        for (int half = 0; half < 2; half++) {   // c0/c1 vs c2/c3 (row, row+8)
            int m = m0 + wm + mt * 16 + qrow + half * 8;
            if (m >= M) continue;
            float gm = 0.f;
            long crow;
            if (SCATTER) { crow = (long)idx[m] * ldc; gm = gate[m]; }
            else         { crow = (long)m * ldc; }
            #pragma unroll
            for (int nt = 0; nt < 4; nt++) {
                int colg = n0 + wn + nt * 8;
                if (colg >= N) continue;
                int col = colg + 2 * qk;
                float v0 = alpha * acc[mt][nt][half * 2 + 0];
                float v1 = alpha * acc[mt][nt][half * 2 + 1];
                float2* cp = (float2*)(C + crow + col);
                if (SCATTER) {
                    float2 old = *cp;
                    old.x += gm * v0; old.y += gm * v1;
                    *cp = old;
                } else if (addC) {
                    float2 old = *cp;
                    old.x += v0; old.y += v1;
                    *cp = old;
                } else {
                    *cp = make_float2(v0, v1);
                }
            }
        }
    }
}

// ---------------- host-side launcher ----------------
struct GArgs {
    const float *A, *B; float* C;
    int M, N, K, lda, ldb, ldc;
    float alpha; int addC, causal;
    const int* idx; const float* gate; const int* Mdev;
    int Z; long sAb, sAh, sBb, sBh, sCb, sCh; int nH, hDiv;
};

static void run_gemm(int mode /*0=NN,1=NT,2=NN gather,3=NN scatter*/, const GArgs& a) {
    dim3 grid((a.N + 127) / 128, (a.M + 127) / 128, a.Z);
    dim3 blk(256);
    switch (mode) {
    case 0:
        gemm_k<false,false,false><<<grid, blk>>>(a.A, a.B, a.C, a.M, a.N, a.K, a.lda, a.ldb,
            a.ldc, a.alpha, a.addC, a.causal, a.idx, a.gate, a.Mdev,
            a.sAb, a.sAh, a.sBb, a.sBh, a.sCb, a.sCh, a.nH, a.hDiv);
        break;
    case 1:
        gemm_k<true,false,false><<<grid, blk>>>(a.A, a.B, a.C, a.M, a.N, a.K, a.lda, a.ldb,
            a.ldc, a.alpha, a.addC, a.causal, a.idx, a.gate, a.Mdev,
            a.sAb, a.sAh, a.sBb, a.sBh, a.sCb, a.sCh, a.nH, a.hDiv);
        break;
    case 2:
        gemm_k<false,true,false><<<grid, blk>>>(a.A, a.B, a.C, a.M, a.N, a.K, a.lda, a.ldb,
            a.ldc, a.alpha, a.addC, a.causal, a.idx, a.gate, a.Mdev,
            a.sAb, a.sAh, a.sBb, a.sBh, a.sCb, a.sCh, a.nH, a.hDiv);
        break;
    default:
        gemm_k<false,false,true><<<grid, blk>>>(a.A, a.B, a.C, a.M, a.N, a.K, a.lda, a.ldb,
            a.ldc, a.alpha, a.addC, a.causal, a.idx, a.gate, a.Mdev,
            a.sAb, a.sAh, a.sBb, a.sBh, a.sCb, a.sCh, a.nH, a.hDiv);
        break;
    }
}

static GArgs base_args() {
    GArgs a;
    a.A = a.B = nullptr; a.C = nullptr;
    a.M = a.N = a.K = a.lda = a.ldb = a.ldc = 0;
    a.alpha = 1.f; a.addC = 0; a.causal = 0;
    a.idx = nullptr; a.gate = nullptr; a.Mdev = nullptr;
    a.Z = 1; a.sAb = a.sAh = a.sBb = a.sBh = a.sCb = a.sCh = 0;
    a.nH = 1; a.hDiv = 1;
    return a;
}

extern "C" void kernel_launch(void* const* d_in, const int* in_sizes, int n_in,
                              void* d_out, int out_size) {
    const int*   tok    = (const int*)d_in[0];
    const int*   pos    = (const int*)d_in[1];
    const float* emb    = (const float*)d_in[2];
    const float* attnw  = (const float*)d_in[3];
    const float* wq     = (const float*)d_in[4];
    const float* wk     = (const float*)d_in[5];
    const float* wv     = (const float*)d_in[6];
    const float* qnw    = (const float*)d_in[7];
    const float* knw    = (const float*)d_in[8];
    const float* wo     = (const float*)d_in[9];
    const float* ffnw   = (const float*)d_in[10];
    const float* rw     = (const float*)d_in[11];
    const float* gw     = (const float*)d_in[12];
    const float* uw     = (const float*)d_in[13];
    const float* dw     = (const float*)d_in[14];
    const float* fnw    = (const float*)d_in[15];
    float* out = (float*)d_out;

    float *px, *ph, *pq, *pk, *pv, *po, *pscores, *pgbuf, *pubuf, *pegate;
    int *peidx, *pecnt;
    cudaGetSymbolAddress((void**)&px, g_x);
    cudaGetSymbolAddress((void**)&ph, g_h);
    cudaGetSymbolAddress((void**)&pq, g_q);
    cudaGetSymbolAddress((void**)&pk, g_k);
    cudaGetSymbolAddress((void**)&pv, g_v);
    cudaGetSymbolAddress((void**)&po, g_o);
    cudaGetSymbolAddress((void**)&pscores, g_scores);
    cudaGetSymbolAddress((void**)&pgbuf, g_gbuf);
    cudaGetSymbolAddress((void**)&pubuf, g_ubuf);
    cudaGetSymbolAddress((void**)&pegate, g_egate);
    cudaGetSymbolAddress((void**)&peidx, g_eidx);
    cudaGetSymbolAddress((void**)&pecnt, g_ecnt);

    // embed
    embed_k<<<(Tt * Dd) / 256, 256>>>(tok, emb, px);

    for (int l = 0; l < Ll; l++) {
        // ---- attention ----
        rmsnorm_k<<<Tt, 256>>>(px, attnw + (long)l * Dd, ph);

        { GArgs a = base_args(); a.A = ph; a.B = wq + (long)l * Dd * (Hh * HDd); a.C = pq;
          a.M = Tt; a.N = Hh * HDd; a.K = Dd; a.lda = Dd; a.ldb = Hh * HDd; a.ldc = Hh * HDd;
          run_gemm(0, a); }
        { GArgs a = base_args(); a.A = ph; a.B = wk + (long)l * Dd * (KVh * HDd); a.C = pk;
          a.M = Tt; a.N = KVh * HDd; a.K = Dd; a.lda = Dd; a.ldb = KVh * HDd; a.ldc = KVh * HDd;
          run_gemm(0, a); }
        { GArgs a = base_args(); a.A = ph; a.B = wv + (long)l * Dd * (KVh * HDd); a.C = pv;
          a.M = Tt; a.N = KVh * HDd; a.K = Dd; a.lda = Dd; a.ldb = KVh * HDd; a.ldc = KVh * HDd;
          run_gemm(0, a); }

        qknorm_rope_k<<<Tt * Hh, 64>>>(pq, qnw + (long)l * HDd, pos, Hh, Hh * HDd);
        qknorm_rope_k<<<Tt * KVh, 64>>>(pk, knw + (long)l * HDd, pos, KVh, KVh * HDd);

        // scores = Q @ K^T * scale  (batched over B*H, GQA h/4, causal tile skip)
        { GArgs a = base_args(); a.A = pq; a.B = pk; a.C = pscores;
          a.M = Ss; a.N = Ss; a.K = HDd; a.lda = Hh * HDd; a.ldb = KVh * HDd; a.ldc = Ss;
          a.alpha = 0.125f; a.causal = 1;
          a.Z = Bz * Hh; a.nH = Hh; a.hDiv = Hh / KVh;
          a.sAb = (long)Ss * Hh * HDd; a.sAh = HDd;
          a.sBb = (long)Ss * KVh * HDd; a.sBh = HDd;
          a.sCb = (long)Hh * Ss * Ss; a.sCh = (long)Ss * Ss;
          run_gemm(1, a); }

        softmax_k<<<Bz * Hh * Ss, 256>>>(pscores);

        // O = P @ V
        { GArgs a = base_args(); a.A = pscores; a.B = pv; a.C = po;
          a.M = Ss; a.N = HDd; a.K = Ss; a.lda = Ss; a.ldb = KVh * HDd; a.ldc = Hh * HDd;
          a.Z = Bz * Hh; a.nH = Hh; a.hDiv = Hh / KVh;
          a.sAb = (long)Hh * Ss * Ss; a.sAh = (long)Ss * Ss;
          a.sBb = (long)Ss * KVh * HDd; a.sBh = HDd;
          a.sCb = (long)Ss * Hh * HDd; a.sCh = HDd;
          run_gemm(0, a); }

        // x += O @ wo
        { GArgs a = base_args(); a.A = po; a.B = wo + (long)l * (Hh * HDd) * Dd; a.C = px;
          a.M = Tt; a.N = Dd; a.K = Hh * HDd; a.lda = Hh * HDd; a.ldb = Dd; a.ldc = Dd;
          a.addC = 1;
          run_gemm(0, a); }

        // ---- MoE ----
        rmsnorm_k<<<Tt, 256>>>(px, ffnw + (long)l * Dd, ph);
        zero_cnt_k<<<1, 32>>>(pecnt);
        router_k<<<Tt, 256>>>(ph, rw + (long)l * Dd * Ee, pecnt, peidx, pegate);

        for (int e = 0; e < Ee; e++) {
            const int* ecnt_e = pecnt + e;
            const int* idx_e = peidx + e * Tt;
            const float* gate_e = pegate + e * Tt;
            long woff = (long)l * Ee * Dd * Ff + (long)e * Dd * Ff;

            { GArgs a = base_args(); a.A = ph; a.B = gw + woff; a.C = pgbuf;
              a.M = Tt; a.N = Ff; a.K = Dd; a.lda = Dd; a.ldb = Ff; a.ldc = Ff;
              a.idx = idx_e; a.Mdev = ecnt_e;
              run_gemm(2, a); }
            { GArgs a = base_args(); a.A = ph; a.B = uw + woff; a.C = pubuf;
              a.M = Tt; a.N = Ff; a.K = Dd; a.lda = Dd; a.ldb = Ff; a.ldc = Ff;
              a.idx = idx_e; a.Mdev = ecnt_e;
              run_gemm(2, a); }
            silu_mul_k<<<(Tt * Ff) / 256, 256>>>(pgbuf, pubuf, ecnt_e);
            // x[idx] += gate * (act @ down_w)
            { GArgs a = base_args(); a.A = pgbuf; a.B = dw + woff; a.C = px;
              a.M = Tt; a.N = Dd; a.K = Ff; a.lda = Ff; a.ldb = Dd; a.ldc = Dd;
              a.idx = idx_e; a.gate = gate_e; a.Mdev = ecnt_e;
              run_gemm(3, a); }
        }
    }

    // final norm + tied lm_head (NT against tok_emb)
    rmsnorm_k<<<Tt, 256>>>(px, fnw, ph);
    { GArgs a = base_args(); a.A = ph; a.B = emb; a.C = out;
      a.M = Tt; a.N = Vv; a.K = Dd; a.lda = Dd; a.ldb = Dd; a.ldc = Vv;
      run_gemm(1, a); }
}

// round 9
// speedup vs baseline: 1.4965x; 1.4965x over previous
#include <cuda_runtime.h>
#include <cuda_bf16.h>
#include <math.h>
#include <stdint.h>

// ---------------- model dims ----------------
#define Bz   2
#define Ss   1024
#define Tt   (Bz*Ss)        // 2048 tokens
#define Dd   1024
#define Hh   16
#define KVh  4
#define HDd  64
#define Ll   4
#define Ee   8
#define Ff   1024
#define Vv   32000

// ---------------- scratch (device globals; no allocation) ----------------
__device__ float g_x[Tt*Dd];
__device__ float g_h[Tt*Dd];
__device__ float g_q[Tt*Hh*HDd];
__device__ float g_k[Tt*KVh*HDd];
__device__ float g_v[Tt*KVh*HDd];
__device__ float g_scores[(size_t)Bz*Hh*Ss*Ss];   // 134 MB
__device__ float g_o[Tt*Hh*HDd];
__device__ float g_gbuf[(size_t)Ee*Tt*Ff];        // 67 MB per-expert gate
__device__ float g_ubuf[(size_t)Ee*Tt*Ff];        // 67 MB per-expert up
__device__ float g_dbuf[(size_t)Ee*Tt*Dd];        // 67 MB per-slot down output
__device__ int   g_eidx[Ee*Tt];
__device__ float g_egate[Ee*Tt];
__device__ int   g_ecnt[Ee];
__device__ int   g_slot[2*Tt];                    // token -> its two (e*Tt+pos) slots

// ---------------- helpers ----------------
__device__ __forceinline__ float tf32r(float x) {
    uint32_t u;
    asm("cvt.rna.tf32.f32 %0, %1;" : "=r"(u) : "f"(x));
    return __uint_as_float(u);
}

__device__ __forceinline__ void mma8(float* c, const uint32_t* a, const uint32_t* b) {
    asm volatile("mma.sync.aligned.m16n8k8.row.col.f32.tf32.tf32.f32 "
                 "{%0,%1,%2,%3}, {%4,%5,%6,%7}, {%8,%9}, {%0,%1,%2,%3};"
                 : "+f"(c[0]), "+f"(c[1]), "+f"(c[2]), "+f"(c[3])
                 : "r"(a[0]), "r"(a[1]), "r"(a[2]), "r"(a[3]),
                   "r"(b[0]), "r"(b[1]));
}

__device__ __forceinline__ float blockReduceSum256(float v) {
    __shared__ float sh[32];
    int lane = threadIdx.x & 31, wid = threadIdx.x >> 5;
    #pragma unroll
    for (int o = 16; o; o >>= 1) v += __shfl_xor_sync(0xffffffffu, v, o);
    if (lane == 0) sh[wid] = v;
    __syncthreads();
    int nw = (blockDim.x + 31) >> 5;
    float r = (threadIdx.x < nw) ? sh[threadIdx.x] : 0.f;
    if (wid == 0) {
        #pragma unroll
        for (int o = 16; o; o >>= 1) r += __shfl_xor_sync(0xffffffffu, r, o);
        if (lane == 0) sh[0] = r;
    }
    __syncthreads();
    float out = sh[0];
    __syncthreads();
    return out;
}

__device__ __forceinline__ float blockReduceMax256(float v) {
    __shared__ float sh[32];
    int lane = threadIdx.x & 31, wid = threadIdx.x >> 5;
    #pragma unroll
    for (int o = 16; o; o >>= 1) v = fmaxf(v, __shfl_xor_sync(0xffffffffu, v, o));
    if (lane == 0) sh[wid] = v;
    __syncthreads();
    int nw = (blockDim.x + 31) >> 5;
    float r = (threadIdx.x < nw) ? sh[threadIdx.x] : -INFINITY;
    if (wid == 0) {
        #pragma unroll
        for (int o = 16; o; o >>= 1) r = fmaxf(r, __shfl_xor_sync(0xffffffffu, r, o));
        if (lane == 0) sh[0] = r;
    }
    __syncthreads();
    float out = sh[0];
    __syncthreads();
    return out;
}

// ---------------- elementwise kernels ----------------
__global__ void embed_k(const int* __restrict__ tok, const float* __restrict__ emb,
                        float* __restrict__ x) {
    int i = blockIdx.x * 256 + threadIdx.x;
    int t = i / Dd, d = i % Dd;
    x[i] = emb[(long)tok[t] * Dd + d];
}

__global__ void rmsnorm_k(const float* __restrict__ x, const float* __restrict__ w,
                          float* __restrict__ out) {
    int row = blockIdx.x;
    const float* xr = x + (long)row * Dd;
    float* orow = out + (long)row * Dd;
    float ss = 0.f;
    #pragma unroll
    for (int i = 0; i < 4; i++) {
        float v = xr[threadIdx.x + i * 256];
        ss += v * v;
    }
    float tot = blockReduceSum256(ss);
    float scale = rsqrtf(tot / (float)Dd + 1e-6f);
    #pragma unroll
    for (int i = 0; i < 4; i++) {
        int d = threadIdx.x + i * 256;
        orow[d] = xr[d] * scale * w[d];
    }
}

// per-head RMSNorm + RoPE, in place. block = 64 threads = one (token, head)
__global__ void qknorm_rope_k(float* __restrict__ qk, const float* __restrict__ nw,
                              const int* __restrict__ pos, int nHeads, int ld) {
    int bid = blockIdx.x;
    int t = bid / nHeads, hh = bid % nHeads;
    float* v = qk + (long)t * ld + hh * HDd;
    int d = threadIdx.x;
    float x = v[d];
    float ss = x * x;
    #pragma unroll
    for (int o = 16; o; o >>= 1) ss += __shfl_xor_sync(0xffffffffu, ss, o);
    __shared__ float s2[2];
    if ((d & 31) == 0) s2[d >> 5] = ss;
    __syncthreads();
    float tot = s2[0] + s2[1];
    float scale = rsqrtf(tot / 64.f + 1e-6f);
    float xn = x * scale * nw[d];
    __shared__ float sh[64];
    sh[d] = xn;
    __syncthreads();
    int p = pos[t];
    int fi = d & 31;
    float inv = powf(1e6f, -(float)fi / 32.f);
    float ang = (float)p * inv;
    float c = cosf(ang), s = sinf(ang);
    float other = (d < 32) ? sh[d + 32] : sh[d - 32];
    float rot = (d < 32) ? -other : other;
    v[d] = xn * c + rot * s;
}

// causal softmax over scores rows; zero-fills j>q
__global__ void softmax_k(float* __restrict__ scores) {
    long row = blockIdx.x;                 // B*H*S rows
    int q = (int)(row % Ss);
    float* p = scores + row * Ss;
    int valid = q + 1;
    float mx = -INFINITY;
    for (int j = threadIdx.x; j < valid; j += 256) mx = fmaxf(mx, p[j]);
    mx = blockReduceMax256(mx);
    float sum = 0.f;
    for (int j = threadIdx.x; j < valid; j += 256) {
        float e = expf(p[j] - mx);
        p[j] = e;
        sum += e;
    }
    sum = blockReduceSum256(sum);
    float inv = 1.f / sum;
    for (int j = threadIdx.x; j < valid; j += 256) p[j] *= inv;
    for (int j = valid + threadIdx.x; j < Ss; j += 256) p[j] = 0.f;
}

__global__ void zero_cnt_k(int* c) { if (threadIdx.x < Ee) c[threadIdx.x] = 0; }

// router: logits = h @ rw [D,E]; top-2; normalize; fill expert lists + token slots
__global__ void router_k(const float* __restrict__ h, const float* __restrict__ rw,
                         int* __restrict__ ecnt, int* __restrict__ eidx,
                         float* __restrict__ egate, int* __restrict__ slot) {
    int t = blockIdx.x;
    int lane = threadIdx.x & 31, w = threadIdx.x >> 5;   // warp per expert
    const float* hr = h + (long)t * Dd;
    float s = 0.f;
    for (int d = lane; d < Dd; d += 32) s += hr[d] * rw[(long)d * Ee + w];
    #pragma unroll
    for (int o = 16; o; o >>= 1) s += __shfl_xor_sync(0xffffffffu, s, o);
    __shared__ float lg[Ee];
    if (lane == 0) lg[w] = s;
    __syncthreads();
    if (threadIdx.x == 0) {
        int a = 0;
        #pragma unroll
        for (int i = 1; i < Ee; i++) if (lg[i] > lg[a]) a = i;
        int b = (a == 0) ? 1 : 0;
        #pragma unroll
        for (int i = 0; i < Ee; i++) if (i != a && lg[i] > lg[b]) b = i;
        float wa = 1.f / (1.f + expf(lg[b] - lg[a]));
        float wb = 1.f - wa;
        int pa = atomicAdd(&ecnt[a], 1);
        eidx[a * Tt + pa] = t; egate[a * Tt + pa] = wa;
        int pb = atomicAdd(&ecnt[b], 1);
        eidx[b * Tt + pb] = t; egate[b * Tt + pb] = wb;
        slot[2 * t + 0] = a * Tt + pa;
        slot[2 * t + 1] = b * Tt + pb;
    }
}

// fused silu*up over ALL experts' staging regions (early-exit on count)
__global__ void silu_all_k(float* __restrict__ g, const float* __restrict__ u,
                           const int* __restrict__ cnt) {
    long i = (long)blockIdx.x * 256 + threadIdx.x;
    int e = (int)(i / ((long)Tt * Ff));
    long rem = i % ((long)Tt * Ff);
    if ((int)(rem / Ff) >= cnt[e]) return;
    float x = g[i];
    g[i] = (x / (1.f + expf(-x))) * u[i];
}

// deterministic combine: x[t] += gate0*dbuf[slot0] + gate1*dbuf[slot1]
__global__ void combine_k(float* __restrict__ x, const float* __restrict__ dbuf,
                          const int* __restrict__ slot, const float* __restrict__ eg) {
    long i = (long)blockIdx.x * 256 + threadIdx.x;   // Tt*Dd
    int t = (int)(i / Dd), d = (int)(i % Dd);
    int s0 = slot[2 * t], s1 = slot[2 * t + 1];
    x[i] += eg[s0] * dbuf[(long)s0 * Dd + d] + eg[s1] * dbuf[(long)s1 * Dd + d];
}

// ---------------- 3xTF32 tensor-core tiled GEMM (64x64 tile) ----------------
// MODE 0: batched heads via z (b=z/nH, h=z%nH; strides sAb/sAh/...)
// MODE 1: dual output; z=0 -> (B,C), z=1 -> (B2,C2)
// MODE 2: expert dual + gather: z -> (e=z>>1, which=z&1); M=Mdev[e];
//         A row m -> A[idx[m]]; B/C from (which? B2/C2 : B/C) + e*stride
// MODE 3: expert single: z=e; M=Mdev[e]; A/B/C += e*stride
// Tile 64x64x16, 128 threads = 4 warps (2x2), warp tile 32x32 via m16n8k8 tf32.
// hi/lo tf32 split at smem-store time (3xTF32). Assumes N%64==0, K%16==0.
template<int MODE, bool TRANSB>
__global__ void __launch_bounds__(128) gemm_k(
    const float* __restrict__ A, const float* __restrict__ B,
    const float* __restrict__ B2, float* __restrict__ C, float* __restrict__ C2,
    int M, int N, int K, int lda, int ldb, int ldc,
    float alpha, int addC, int causal,
    const int* __restrict__ idxBase, const int* __restrict__ MdevBase,
    long sAb, long sAh, long sBb, long sBh, long sCb, long sCh,
    int nH, int hDiv, long eA, long eB, long eC)
{
    const int* idx = nullptr;
    if (MODE == 0) {
        int z = blockIdx.z;
        int b = z / nH, h = z % nH;
        A += (long)b * sAb + (long)h * sAh;
        B += (long)b * sBb + (long)(h / hDiv) * sBh;
        C += (long)b * sCb + (long)h * sCh;
    } else if (MODE == 1) {
        if (blockIdx.z) { B = B2; C = C2; }
    } else if (MODE == 2) {
        int e = blockIdx.z >> 1, which = blockIdx.z & 1;
        M = MdevBase[e];
        idx = idxBase + e * Tt;
        B = (which ? B2 : B) + (long)e * eB;
        C = (which ? C2 : C) + (long)e * eC;
    } else {
        int e = blockIdx.z;
        M = MdevBase[e];
        A += (long)e * eA;
        B += (long)e * eB;
        C += (long)e * eC;
    }
    constexpr bool GATHER = (MODE == 2);

    int m0 = blockIdx.y * 64, n0 = blockIdx.x * 64;
    if (m0 >= M) return;
    if (causal && n0 >= m0 + 64) return;

    __shared__ float As[2][2][64][20];   // [buf][hi/lo]; stride 20 conflict-free
    __shared__ float Bs[2][2][16][72];   // stride 72 conflict-free

    int tid = threadIdx.x;
    int lane = tid & 31, warp = tid >> 5;
    int wm = (warp >> 1) * 32, wn = (warp & 1) * 32;
    int qrow = lane >> 2, qk = lane & 3;

    // A global-load geometry: 2 rows x float4 per thread
    int ar_r = tid >> 2;               // 0..31
    int ac4 = (tid & 3) * 4;
    int gr0 = m0 + ar_r, gr1 = gr0 + 32;
    bool av0 = gr0 < M, av1 = gr1 < M;
    long arow0 = 0, arow1 = 0;
    if (av0) arow0 = (long)(GATHER ? idx[gr0] : gr0) * lda;
    if (av1) arow1 = (long)(GATHER ? idx[gr1] : gr1) * lda;

    // B global-load geometry
    int bnr, bc4;
    if (TRANSB) { bnr = tid >> 2; bc4 = (tid & 3) * 4; }   // n-row 0..31(+32), k-col
    else        { bnr = tid >> 4; bc4 = (tid & 15) * 4; }  // k-row 0..7(+8), n-col

    float4 pa0, pa1, pb0, pb1;
    const float4 z4 = make_float4(0.f, 0.f, 0.f, 0.f);

    float acc[2][4][4];
    #pragma unroll
    for (int mt = 0; mt < 2; mt++)
        #pragma unroll
        for (int nt = 0; nt < 4; nt++)
            #pragma unroll
            for (int i = 0; i < 4; i++) acc[mt][nt][i] = 0.f;

    auto LDG = [&](int k0) {
        pa0 = av0 ? *(const float4*)(A + arow0 + k0 + ac4) : z4;
        pa1 = av1 ? *(const float4*)(A + arow1 + k0 + ac4) : z4;
        if (TRANSB) {
            pb0 = *(const float4*)(B + (long)(n0 + bnr) * ldb + k0 + bc4);
            pb1 = *(const float4*)(B + (long)(n0 + bnr + 32) * ldb + k0 + bc4);
        } else {
            pb0 = *(const float4*)(B + (long)(k0 + bnr) * ldb + n0 + bc4);
            pb1 = *(const float4*)(B + (long)(k0 + bnr + 8) * ldb + n0 + bc4);
        }
    };

    auto put = [&](float* hi, float* lo, float v) {
        float h = tf32r(v);
        *hi = h;
        *lo = tf32r(v - h);
    };

    auto STS = [&](int buf) {
        put(&As[buf][0][ar_r][ac4 + 0], &As[buf][1][ar_r][ac4 + 0], pa0.x);
        put(&As[buf][0][ar_r][ac4 + 1], &As[buf][1][ar_r][ac4 + 1], pa0.y);
        put(&As[buf][0][ar_r][ac4 + 2], &As[buf][1][ar_r][ac4 + 2], pa0.z);
        put(&As[buf][0][ar_r][ac4 + 3], &As[buf][1][ar_r][ac4 + 3], pa0.w);
        put(&As[buf][0][ar_r + 32][ac4 + 0], &As[buf][1][ar_r + 32][ac4 + 0], pa1.x);
        put(&As[buf][0][ar_r + 32][ac4 + 1], &As[buf][1][ar_r + 32][ac4 + 1], pa1.y);
        put(&As[buf][0][ar_r + 32][ac4 + 2], &As[buf][1][ar_r + 32][ac4 + 2], pa1.z);
        put(&As[buf][0][ar_r + 32][ac4 + 3], &As[buf][1][ar_r + 32][ac4 + 3], pa1.w);
        if (TRANSB) {
            put(&Bs[buf][0][bc4 + 0][bnr], &Bs[buf][1][bc4 + 0][bnr], pb0.x);
            put(&Bs[buf][0][bc4 + 1][bnr], &Bs[buf][1][bc4 + 1][bnr], pb0.y);
            put(&Bs[buf][0][bc4 + 2][bnr], &Bs[buf][1][bc4 + 2][bnr], pb0.z);
            put(&Bs[buf][0][bc4 + 3][bnr], &Bs[buf][1][bc4 + 3][bnr], pb0.w);
            put(&Bs[buf][0][bc4 + 0][bnr + 32], &Bs[buf][1][bc4 + 0][bnr + 32], pb1.x);
            put(&Bs[buf][0][bc4 + 1][bnr + 32], &Bs[buf][1][bc4 + 1][bnr + 32], pb1.y);
            put(&Bs[buf][0][bc4 + 2][bnr + 32], &Bs[buf][1][bc4 + 2][bnr + 32], pb1.z);
            put(&Bs[buf][0][bc4 + 3][bnr + 32], &Bs[buf][1][bc4 + 3][bnr + 32], pb1.w);
        } else {
            put(&Bs[buf][0][bnr][bc4 + 0], &Bs[buf][1][bnr][bc4 + 0], pb0.x);
            put(&Bs[buf][0][bnr][bc4 + 1], &Bs[buf][1][bnr][bc4 + 1], pb0.y);
            put(&Bs[buf][0][bnr][bc4 + 2], &Bs[buf][1][bnr][bc4 + 2], pb0.z);
            put(&Bs[buf][0][bnr][bc4 + 3], &Bs[buf][1][bnr][bc4 + 3], pb0.w);
            put(&Bs[buf][0][bnr + 8][bc4 + 0], &Bs[buf][1][bnr + 8][bc4 + 0], pb1.x);
            put(&Bs[buf][0][bnr + 8][bc4 + 1], &Bs[buf][1][bnr + 8][bc4 + 1], pb1.y);
            put(&Bs[buf][0][bnr + 8][bc4 + 2], &Bs[buf][1][bnr + 8][bc4 + 2], pb1.z);
            put(&Bs[buf][0][bnr + 8][bc4 + 3], &Bs[buf][1][bnr + 8][bc4 + 3], pb1.w);
        }
    };

    auto COMPUTE = [&](int buf) {
        #pragma unroll
        for (int ks = 0; ks < 2; ks++) {
            int kk = ks * 8 + qk;
            uint32_t afh[2][4], afl[2][4];
            #pragma unroll
            for (int mt = 0; mt < 2; mt++) {
                int r = wm + mt * 16 + qrow;
                afh[mt][0] = __float_as_uint(As[buf][0][r][kk]);
                afh[mt][1] = __float_as_uint(As[buf][0][r + 8][kk]);
                afh[mt][2] = __float_as_uint(As[buf][0][r][kk + 4]);
                afh[mt][3] = __float_as_uint(As[buf][0][r + 8][kk + 4]);
                afl[mt][0] = __float_as_uint(As[buf][1][r][kk]);
                afl[mt][1] = __float_as_uint(As[buf][1][r + 8][kk]);
                afl[mt][2] = __float_as_uint(As[buf][1][r][kk + 4]);
                afl[mt][3] = __float_as_uint(As[buf][1][r + 8][kk + 4]);
            }
            uint32_t bfh[4][2], bfl[4][2];
            #pragma unroll
            for (int nt = 0; nt < 4; nt++) {
                int cn = wn + nt * 8 + qrow;
                bfh[nt][0] = __float_as_uint(Bs[buf][0][kk][cn]);
                bfh[nt][1] = __float_as_uint(Bs[buf][0][kk + 4][cn]);
                bfl[nt][0] = __float_as_uint(Bs[buf][1][kk][cn]);
                bfl[nt][1] = __float_as_uint(Bs[buf][1][kk + 4][cn]);
            }
            #pragma unroll
            for (int mt = 0; mt < 2; mt++)
                #pragma unroll
                for (int nt = 0; nt < 4; nt++) {
                    mma8(acc[mt][nt], afh[mt], bfl[nt]);   // hi*lo
                    mma8(acc[mt][nt], afl[mt], bfh[nt]);   // lo*hi
                    mma8(acc[mt][nt], afh[mt], bfh[nt]);   // hi*hi
                }
        }
    };

    int KT = K >> 4;
    LDG(0);
    STS(0);
    __syncthreads();
    for (int kt = 0; kt < KT; kt++) {
        int cur = kt & 1;
        bool more = (kt + 1) < KT;
        if (more) LDG((kt + 1) * 16);
        COMPUTE(cur);
        if (more) {
            __syncthreads();
            STS(cur ^ 1);
            __syncthreads();
        }
    }

    // ---- epilogue ----
    #pragma unroll
    for (int mt = 0; mt < 2; mt++) {
        #pragma unroll
        for (int half = 0; half < 2; half++) {   // c0/c1 vs c2/c3 (row, row+8)
            int m = m0 + wm + mt * 16 + qrow + half * 8;
            if (m >= M) continue;
            long crow = (long)m * ldc;
            #pragma unroll
            for (int nt = 0; nt < 4; nt++) {
                int col = n0 + wn + nt * 8 + 2 * qk;
                float v0 = alpha * acc[mt][nt][half * 2 + 0];
                float v1 = alpha * acc[mt][nt][half * 2 + 1];
                float2* cp = (float2*)(C + crow + col);
                if (addC) {
                    float2 old = *cp;
                    old.x += v0; old.y += v1;
                    *cp = old;
                } else {
                    *cp = make_float2(v0, v1);
                }
            }
        }
    }
}

// ---------------- host side ----------------
extern "C" void kernel_launch(void* const* d_in, const int* in_sizes, int n_in,
                              void* d_out, int out_size) {
    const int*   tok    = (const int*)d_in[0];
    const int*   pos    = (const int*)d_in[1];
    const float* emb    = (const float*)d_in[2];
    const float* attnw  = (const float*)d_in[3];
    const float* wq     = (const float*)d_in[4];
    const float* wk     = (const float*)d_in[5];
    const float* wv     = (const float*)d_in[6];
    const float* qnw    = (const float*)d_in[7];
    const float* knw    = (const float*)d_in[8];
    const float* wo     = (const float*)d_in[9];
    const float* ffnw   = (const float*)d_in[10];
    const float* rw     = (const float*)d_in[11];
    const float* gw     = (const float*)d_in[12];
    const float* uw     = (const float*)d_in[13];
    const float* dw     = (const float*)d_in[14];
    const float* fnw    = (const float*)d_in[15];
    float* out = (float*)d_out;

    float *px, *ph, *pq, *pk, *pv, *po, *pscores, *pgbuf, *pubuf, *pdbuf, *pegate;
    int *peidx, *pecnt, *pslot;
    cudaGetSymbolAddress((void**)&px, g_x);
    cudaGetSymbolAddress((void**)&ph, g_h);
    cudaGetSymbolAddress((void**)&pq, g_q);
    cudaGetSymbolAddress((void**)&pk, g_k);
    cudaGetSymbolAddress((void**)&pv, g_v);
    cudaGetSymbolAddress((void**)&po, g_o);
    cudaGetSymbolAddress((void**)&pscores, g_scores);
    cudaGetSymbolAddress((void**)&pgbuf, g_gbuf);
    cudaGetSymbolAddress((void**)&pubuf, g_ubuf);
    cudaGetSymbolAddress((void**)&pdbuf, g_dbuf);
    cudaGetSymbolAddress((void**)&pegate, g_egate);
    cudaGetSymbolAddress((void**)&peidx, g_eidx);
    cudaGetSymbolAddress((void**)&pecnt, g_ecnt);
    cudaGetSymbolAddress((void**)&pslot, g_slot);

    const long ZL = 0;

    // embed
    embed_k<<<(Tt * Dd) / 256, 256>>>(tok, emb, px);

    for (int l = 0; l < Ll; l++) {
        const float* wq_l = wq + (long)l * Dd * (Hh * HDd);
        const float* wk_l = wk + (long)l * Dd * (KVh * HDd);
        const float* wv_l = wv + (long)l * Dd * (KVh * HDd);
        const float* wo_l = wo + (long)l * (Hh * HDd) * Dd;
        const float* gw_l = gw + (long)l * Ee * Dd * Ff;
        const float* uw_l = uw + (long)l * Ee * Dd * Ff;
        const float* dw_l = dw + (long)l * Ee * Ff * Dd;

        // ---- attention ----
        rmsnorm_k<<<Tt, 256>>>(px, attnw + (long)l * Dd, ph);

        // Q projection
        gemm_k<0,false><<<dim3(16, 32, 1), 128>>>(
            ph, wq_l, nullptr, pq, nullptr,
            Tt, Hh * HDd, Dd, Dd, Hh * HDd, Hh * HDd,
            1.f, 0, 0, nullptr, nullptr,
            ZL, ZL, ZL, ZL, ZL, ZL, 1, 1, ZL, ZL, ZL);

        // K + V fused (dual output over z)
        gemm_k<1,false><<<dim3(4, 32, 2), 128>>>(
            ph, wk_l, wv_l, pk, pv,
            Tt, KVh * HDd, Dd, Dd, KVh * HDd, KVh * HDd,
            1.f, 0, 0, nullptr, nullptr,
            ZL, ZL, ZL, ZL, ZL, ZL, 1, 1, ZL, ZL, ZL);

        qknorm_rope_k<<<Tt * Hh, 64>>>(pq, qnw + (long)l * HDd, pos, Hh, Hh * HDd);
        qknorm_rope_k<<<Tt * KVh, 64>>>(pk, knw + (long)l * HDd, pos, KVh, KVh * HDd);

        // scores = Q @ K^T * scale  (batched over B*H, GQA, causal tile skip)
        gemm_k<0,true><<<dim3(16, 16, Bz * Hh), 128>>>(
            pq, pk, nullptr, pscores, nullptr,
            Ss, Ss, HDd, Hh * HDd, KVh * HDd, Ss,
            0.125f, 0, 1, nullptr, nullptr,
            (long)Ss * Hh * HDd, (long)HDd,
            (long)Ss * KVh * HDd, (long)HDd,
            (long)Hh * Ss * Ss, (long)Ss * Ss,
            Hh, Hh / KVh, ZL, ZL, ZL);

        softmax_k<<<Bz * Hh * Ss, 256>>>(pscores);

        // O = P @ V
        gemm_k<0,false><<<dim3(1, 16, Bz * Hh), 128>>>(
            pscores, pv, nullptr, po, nullptr,
            Ss, HDd, Ss, Ss, KVh * HDd, Hh * HDd,
            1.f, 0, 0, nullptr, nullptr,
            (long)Hh * Ss * Ss, (long)Ss * Ss,
            (long)Ss * KVh * HDd, (long)HDd,
            (long)Ss * Hh * HDd, (long)HDd,
            Hh, Hh / KVh, ZL, ZL, ZL);

        // x += O @ wo
        gemm_k<0,false><<<dim3(16, 32, 1), 128>>>(
            po, wo_l, nullptr, px, nullptr,
            Tt, Dd, Hh * HDd, Hh * HDd, Dd, Dd,
            1.f, 1, 0, nullptr, nullptr,
            ZL, ZL, ZL, ZL, ZL, ZL, 1, 1, ZL, ZL, ZL);

        // ---- MoE ----
        rmsnorm_k<<<Tt, 256>>>(px, ffnw + (long)l * Dd, ph);
        zero_cnt_k<<<1, 32>>>(pecnt);
        router_k<<<Tt, 256>>>(ph, rw + (long)l * Dd * Ee, pecnt, peidx, pegate, pslot);

        // all experts' gate+up in ONE launch: z = e*2 + which
        gemm_k<2,false><<<dim3(16, 32, 2 * Ee), 128>>>(
            ph, gw_l, uw_l, pgbuf, pubuf,
            Tt, Ff, Dd, Dd, Ff, Ff,
            1.f, 0, 0, peidx, pecnt,
            ZL, ZL, ZL, ZL, ZL, ZL, 1, 1,
            ZL, (long)Dd * Ff, (long)Tt * Ff);

        // fused silu*up over all experts
        silu_all_k<<<(int)(((long)Ee * Tt * Ff) / 256), 256>>>(pgbuf, pubuf, pecnt);

        // all experts' down-proj in ONE launch -> per-slot buffer
        gemm_k<3,false><<<dim3(16, 32, Ee), 128>>>(
            pgbuf, dw_l, nullptr, pdbuf, nullptr,
            Tt, Dd, Ff, Ff, Dd, Dd,
            1.f, 0, 0, nullptr, pecnt,
            ZL, ZL, ZL, ZL, ZL, ZL, 1, 1,
            (long)Tt * Ff, (long)Ff * Dd, (long)Tt * Dd);

        // deterministic combine: x += gate0*y0 + gate1*y1
        combine_k<<<(Tt * Dd) / 256, 256>>>(px, pdbuf, pslot, pegate);
    }

    // final norm + tied lm_head (NT against tok_emb)
    rmsnorm_k<<<Tt, 256>>>(px, fnw, ph);
    gemm_k<0,true><<<dim3(Vv / 64, 32, 1), 128>>>(
        ph, emb, nullptr, out, nullptr,
        Tt, Vv, Dd, Dd, Dd, Vv,
        1.f, 0, 0, nullptr, nullptr,
        ZL, ZL, ZL, ZL, ZL, ZL, 1, 1, ZL, ZL, ZL);
}

// round 10
// speedup vs baseline: 1.8637x; 1.2454x over previous
#include <cuda_runtime.h>
#include <cuda_bf16.h>
#include <math.h>
#include <stdint.h>

// ---------------- model dims ----------------
#define Bz   2
#define Ss   1024
#define Tt   (Bz*Ss)        // 2048 tokens
#define Dd   1024
#define Hh   16
#define KVh  4
#define HDd  64
#define Ll   4
#define Ee   8
#define Ff   1024
#define Vv   32000

// ---------------- scratch (device globals; no allocation) ----------------
__device__ float g_x[Tt*Dd];
__device__ float g_h[Tt*Dd];
__device__ float g_q[Tt*Hh*HDd];
__device__ float g_k[Tt*KVh*HDd];
__device__ float g_v[Tt*KVh*HDd];
__device__ float g_scores[(size_t)Bz*Hh*Ss*Ss];   // 134 MB
__device__ float g_o[Tt*Hh*HDd];
__device__ float g_gbuf[(size_t)Ee*Tt*Ff];        // 67 MB per-expert gate
__device__ float g_ubuf[(size_t)Ee*Tt*Ff];        // 67 MB per-expert up
__device__ float g_dbuf[(size_t)Ee*Tt*Dd];        // 67 MB per-slot down output
__device__ int   g_eidx[Ee*Tt];
__device__ float g_egate[Ee*Tt];
__device__ int   g_ecnt[Ee];
__device__ int   g_slot[2*Tt];                    // token -> its two (e*Tt+pos) slots

// ---------------- helpers ----------------
__device__ __forceinline__ float tf32r(float x) {
    uint32_t u;
    asm("cvt.rna.tf32.f32 %0, %1;" : "=r"(u) : "f"(x));
    return __uint_as_float(u);
}

__device__ __forceinline__ void mma8(float* c, const uint32_t* a, const uint32_t* b) {
    asm volatile("mma.sync.aligned.m16n8k8.row.col.f32.tf32.tf32.f32 "
                 "{%0,%1,%2,%3}, {%4,%5,%6,%7}, {%8,%9}, {%0,%1,%2,%3};"
                 : "+f"(c[0]), "+f"(c[1]), "+f"(c[2]), "+f"(c[3])
                 : "r"(a[0]), "r"(a[1]), "r"(a[2]), "r"(a[3]),
                   "r"(b[0]), "r"(b[1]));
}

__device__ __forceinline__ float blockReduceSum256(float v) {
    __shared__ float sh[32];
    int lane = threadIdx.x & 31, wid = threadIdx.x >> 5;
    #pragma unroll
    for (int o = 16; o; o >>= 1) v += __shfl_xor_sync(0xffffffffu, v, o);
    if (lane == 0) sh[wid] = v;
    __syncthreads();
    int nw = (blockDim.x + 31) >> 5;
    float r = (threadIdx.x < nw) ? sh[threadIdx.x] : 0.f;
    if (wid == 0) {
        #pragma unroll
        for (int o = 16; o; o >>= 1) r += __shfl_xor_sync(0xffffffffu, r, o);
        if (lane == 0) sh[0] = r;
    }
    __syncthreads();
    float out = sh[0];
    __syncthreads();
    return out;
}

__device__ __forceinline__ float blockReduceMax256(float v) {
    __shared__ float sh[32];
    int lane = threadIdx.x & 31, wid = threadIdx.x >> 5;
    #pragma unroll
    for (int o = 16; o; o >>= 1) v = fmaxf(v, __shfl_xor_sync(0xffffffffu, v, o));
    if (lane == 0) sh[wid] = v;
    __syncthreads();
    int nw = (blockDim.x + 31) >> 5;
    float r = (threadIdx.x < nw) ? sh[threadIdx.x] : -INFINITY;
    if (wid == 0) {
        #pragma unroll
        for (int o = 16; o; o >>= 1) r = fmaxf(r, __shfl_xor_sync(0xffffffffu, r, o));
        if (lane == 0) sh[0] = r;
    }
    __syncthreads();
    float out = sh[0];
    __syncthreads();
    return out;
}

// ---------------- elementwise kernels ----------------
__global__ void embed_k(const int* __restrict__ tok, const float* __restrict__ emb,
                        float* __restrict__ x) {
    int i = blockIdx.x * 256 + threadIdx.x;
    int t = i / Dd, d = i % Dd;
    x[i] = emb[(long)tok[t] * Dd + d];
}

__global__ void rmsnorm_k(const float* __restrict__ x, const float* __restrict__ w,
                          float* __restrict__ out) {
    int row = blockIdx.x;
    const float* xr = x + (long)row * Dd;
    float* orow = out + (long)row * Dd;
    float ss = 0.f;
    #pragma unroll
    for (int i = 0; i < 4; i++) {
        float v = xr[threadIdx.x + i * 256];
        ss += v * v;
    }
    float tot = blockReduceSum256(ss);
    float scale = rsqrtf(tot / (float)Dd + 1e-6f);
    #pragma unroll
    for (int i = 0; i < 4; i++) {
        int d = threadIdx.x + i * 256;
        orow[d] = xr[d] * scale * w[d];
    }
}

// per-head RMSNorm + RoPE, in place. block = 64 threads = one (token, head)
__global__ void qknorm_rope_k(float* __restrict__ qk, const float* __restrict__ nw,
                              const int* __restrict__ pos, int nHeads, int ld) {
    int bid = blockIdx.x;
    int t = bid / nHeads, hh = bid % nHeads;
    float* v = qk + (long)t * ld + hh * HDd;
    int d = threadIdx.x;
    float x = v[d];
    float ss = x * x;
    #pragma unroll
    for (int o = 16; o; o >>= 1) ss += __shfl_xor_sync(0xffffffffu, ss, o);
    __shared__ float s2[2];
    if ((d & 31) == 0) s2[d >> 5] = ss;
    __syncthreads();
    float tot = s2[0] + s2[1];
    float scale = rsqrtf(tot / 64.f + 1e-6f);
    float xn = x * scale * nw[d];
    __shared__ float sh[64];
    sh[d] = xn;
    __syncthreads();
    int p = pos[t];
    int fi = d & 31;
    float inv = powf(1e6f, -(float)fi / 32.f);
    float ang = (float)p * inv;
    float c = cosf(ang), s = sinf(ang);
    float other = (d < 32) ? sh[d + 32] : sh[d - 32];
    float rot = (d < 32) ? -other : other;
    v[d] = xn * c + rot * s;
}

// causal softmax over scores rows; zero-fills j>q
__global__ void softmax_k(float* __restrict__ scores) {
    long row = blockIdx.x;                 // B*H*S rows
    int q = (int)(row % Ss);
    float* p = scores + row * Ss;
    int valid = q + 1;
    float mx = -INFINITY;
    for (int j = threadIdx.x; j < valid; j += 256) mx = fmaxf(mx, p[j]);
    mx = blockReduceMax256(mx);
    float sum = 0.f;
    for (int j = threadIdx.x; j < valid; j += 256) {
        float e = expf(p[j] - mx);
        p[j] = e;
        sum += e;
    }
    sum = blockReduceSum256(sum);
    float inv = 1.f / sum;
    for (int j = threadIdx.x; j < valid; j += 256) p[j] *= inv;
    for (int j = valid + threadIdx.x; j < Ss; j += 256) p[j] = 0.f;
}

__global__ void zero_cnt_k(int* c) { if (threadIdx.x < Ee) c[threadIdx.x] = 0; }

// router: logits = h @ rw [D,E]; top-2; normalize; fill expert lists + token slots
__global__ void router_k(const float* __restrict__ h, const float* __restrict__ rw,
                         int* __restrict__ ecnt, int* __restrict__ eidx,
                         float* __restrict__ egate, int* __restrict__ slot) {
    int t = blockIdx.x;
    int lane = threadIdx.x & 31, w = threadIdx.x >> 5;   // warp per expert
    const float* hr = h + (long)t * Dd;
    float s = 0.f;
    for (int d = lane; d < Dd; d += 32) s += hr[d] * rw[(long)d * Ee + w];
    #pragma unroll
    for (int o = 16; o; o >>= 1) s += __shfl_xor_sync(0xffffffffu, s, o);
    __shared__ float lg[Ee];
    if (lane == 0) lg[w] = s;
    __syncthreads();
    if (threadIdx.x == 0) {
        int a = 0;
        #pragma unroll
        for (int i = 1; i < Ee; i++) if (lg[i] > lg[a]) a = i;
        int b = (a == 0) ? 1 : 0;
        #pragma unroll
        for (int i = 0; i < Ee; i++) if (i != a && lg[i] > lg[b]) b = i;
        float wa = 1.f / (1.f + expf(lg[b] - lg[a]));
        float wb = 1.f - wa;
        int pa = atomicAdd(&ecnt[a], 1);
        eidx[a * Tt + pa] = t; egate[a * Tt + pa] = wa;
        int pb = atomicAdd(&ecnt[b], 1);
        eidx[b * Tt + pb] = t; egate[b * Tt + pb] = wb;
        slot[2 * t + 0] = a * Tt + pa;
        slot[2 * t + 1] = b * Tt + pb;
    }
}

// fused silu*up over ALL experts' staging regions (early-exit on count)
__global__ void silu_all_k(float* __restrict__ g, const float* __restrict__ u,
                           const int* __restrict__ cnt) {
    long i = (long)blockIdx.x * 256 + threadIdx.x;
    int e = (int)(i / ((long)Tt * Ff));
    long rem = i % ((long)Tt * Ff);
    if ((int)(rem / Ff) >= cnt[e]) return;
    float x = g[i];
    g[i] = (x / (1.f + expf(-x))) * u[i];
}

// deterministic combine: x[t] += gate0*dbuf[slot0] + gate1*dbuf[slot1]
__global__ void combine_k(float* __restrict__ x, const float* __restrict__ dbuf,
                          const int* __restrict__ slot, const float* __restrict__ eg) {
    long i = (long)blockIdx.x * 256 + threadIdx.x;   // Tt*Dd
    int t = (int)(i / Dd), d = (int)(i % Dd);
    int s0 = slot[2 * t], s1 = slot[2 * t + 1];
    x[i] += eg[s0] * dbuf[(long)s0 * Dd + d] + eg[s1] * dbuf[(long)s1 * Dd + d];
}

// ========== MODE semantics (both GEMM kernels) ==========
// MODE 0: batched heads via z (b=z/nH, h=z%nH; strides sAb/sAh/...)
// MODE 1: dual output; z=0 -> (B,C), z=1 -> (B2,C2)
// MODE 2: expert dual + gather: z -> (e=z>>1, which=z&1); M=Mdev[e];
//         A row m -> A[idx[m]]; B/C from (which? B2/C2 : B/C) + e*stride
// MODE 3: expert single: z=e; M=Mdev[e]; A/B/C += e*stride

// ---------------- 3xTF32 GEMM, 64x64 tile (small/batched shapes) ----------------
// 128 threads = 4 warps (2x2), warp tile 32x32. hi/lo split at STS. N%64==0,K%16==0.
template<int MODE, bool TRANSB>
__global__ void __launch_bounds__(128) gemm64_k(
    const float* __restrict__ A, const float* __restrict__ B,
    const float* __restrict__ B2, float* __restrict__ C, float* __restrict__ C2,
    int M, int N, int K, int lda, int ldb, int ldc,
    float alpha, int addC, int causal,
    const int* __restrict__ idxBase, const int* __restrict__ MdevBase,
    long sAb, long sAh, long sBb, long sBh, long sCb, long sCh,
    int nH, int hDiv, long eA, long eB, long eC)
{
    const int* idx = nullptr;
    if (MODE == 0) {
        int z = blockIdx.z;
        int b = z / nH, h = z % nH;
        A += (long)b * sAb + (long)h * sAh;
        B += (long)b * sBb + (long)(h / hDiv) * sBh;
        C += (long)b * sCb + (long)h * sCh;
    } else if (MODE == 1) {
        if (blockIdx.z) { B = B2; C = C2; }
    } else if (MODE == 2) {
        int e = blockIdx.z >> 1, which = blockIdx.z & 1;
        M = MdevBase[e];
        idx = idxBase + e * Tt;
        B = (which ? B2 : B) + (long)e * eB;
        C = (which ? C2 : C) + (long)e * eC;
    } else {
        int e = blockIdx.z;
        M = MdevBase[e];
        A += (long)e * eA;
        B += (long)e * eB;
        C += (long)e * eC;
    }
    constexpr bool GATHER = (MODE == 2);

    int m0 = blockIdx.y * 64, n0 = blockIdx.x * 64;
    if (m0 >= M) return;
    if (causal && n0 >= m0 + 64) return;

    __shared__ float As[2][2][64][20];
    __shared__ float Bs[2][2][16][72];

    int tid = threadIdx.x;
    int lane = tid & 31, warp = tid >> 5;
    int wm = (warp >> 1) * 32, wn = (warp & 1) * 32;
    int qrow = lane >> 2, qk = lane & 3;

    int ar_r = tid >> 2;
    int ac4 = (tid & 3) * 4;
    int gr0 = m0 + ar_r, gr1 = gr0 + 32;
    bool av0 = gr0 < M, av1 = gr1 < M;
    long arow0 = 0, arow1 = 0;
    if (av0) arow0 = (long)(GATHER ? idx[gr0] : gr0) * lda;
    if (av1) arow1 = (long)(GATHER ? idx[gr1] : gr1) * lda;

    int bnr, bc4;
    if (TRANSB) { bnr = tid >> 2; bc4 = (tid & 3) * 4; }
    else        { bnr = tid >> 4; bc4 = (tid & 15) * 4; }

    float4 pa0, pa1, pb0, pb1;
    const float4 z4 = make_float4(0.f, 0.f, 0.f, 0.f);

    float acc[2][4][4];
    #pragma unroll
    for (int mt = 0; mt < 2; mt++)
        #pragma unroll
        for (int nt = 0; nt < 4; nt++)
            #pragma unroll
            for (int i = 0; i < 4; i++) acc[mt][nt][i] = 0.f;

    auto LDG = [&](int k0) {
        pa0 = av0 ? *(const float4*)(A + arow0 + k0 + ac4) : z4;
        pa1 = av1 ? *(const float4*)(A + arow1 + k0 + ac4) : z4;
        if (TRANSB) {
            pb0 = *(const float4*)(B + (long)(n0 + bnr) * ldb + k0 + bc4);
            pb1 = *(const float4*)(B + (long)(n0 + bnr + 32) * ldb + k0 + bc4);
        } else {
            pb0 = *(const float4*)(B + (long)(k0 + bnr) * ldb + n0 + bc4);
            pb1 = *(const float4*)(B + (long)(k0 + bnr + 8) * ldb + n0 + bc4);
        }
    };

    auto put = [&](float* hi, float* lo, float v) {
        float h = tf32r(v);
        *hi = h;
        *lo = tf32r(v - h);
    };

    auto STS = [&](int buf) {
        put(&As[buf][0][ar_r][ac4 + 0], &As[buf][1][ar_r][ac4 + 0], pa0.x);
        put(&As[buf][0][ar_r][ac4 + 1], &As[buf][1][ar_r][ac4 + 1], pa0.y);
        put(&As[buf][0][ar_r][ac4 + 2], &As[buf][1][ar_r][ac4 + 2], pa0.z);
        put(&As[buf][0][ar_r][ac4 + 3], &As[buf][1][ar_r][ac4 + 3], pa0.w);
        put(&As[buf][0][ar_r + 32][ac4 + 0], &As[buf][1][ar_r + 32][ac4 + 0], pa1.x);
        put(&As[buf][0][ar_r + 32][ac4 + 1], &As[buf][1][ar_r + 32][ac4 + 1], pa1.y);
        put(&As[buf][0][ar_r + 32][ac4 + 2], &As[buf][1][ar_r + 32][ac4 + 2], pa1.z);
        put(&As[buf][0][ar_r + 32][ac4 + 3], &As[buf][1][ar_r + 32][ac4 + 3], pa1.w);
        if (TRANSB) {
            put(&Bs[buf][0][bc4 + 0][bnr], &Bs[buf][1][bc4 + 0][bnr], pb0.x);
            put(&Bs[buf][0][bc4 + 1][bnr], &Bs[buf][1][bc4 + 1][bnr], pb0.y);
            put(&Bs[buf][0][bc4 + 2][bnr], &Bs[buf][1][bc4 + 2][bnr], pb0.z);
            put(&Bs[buf][0][bc4 + 3][bnr], &Bs[buf][1][bc4 + 3][bnr], pb0.w);
            put(&Bs[buf][0][bc4 + 0][bnr + 32], &Bs[buf][1][bc4 + 0][bnr + 32], pb1.x);
            put(&Bs[buf][0][bc4 + 1][bnr + 32], &Bs[buf][1][bc4 + 1][bnr + 32], pb1.y);
            put(&Bs[buf][0][bc4 + 2][bnr + 32], &Bs[buf][1][bc4 + 2][bnr + 32], pb1.z);
            put(&Bs[buf][0][bc4 + 3][bnr + 32], &Bs[buf][1][bc4 + 3][bnr + 32], pb1.w);
        } else {
            put(&Bs[buf][0][bnr][bc4 + 0], &Bs[buf][1][bnr][bc4 + 0], pb0.x);
            put(&Bs[buf][0][bnr][bc4 + 1], &Bs[buf][1][bnr][bc4 + 1], pb0.y);
            put(&Bs[buf][0][bnr][bc4 + 2], &Bs[buf][1][bnr][bc4 + 2], pb0.z);
            put(&Bs[buf][0][bnr][bc4 + 3], &Bs[buf][1][bnr][bc4 + 3], pb0.w);
            put(&Bs[buf][0][bnr + 8][bc4 + 0], &Bs[buf][1][bnr + 8][bc4 + 0], pb1.x);
            put(&Bs[buf][0][bnr + 8][bc4 + 1], &Bs[buf][1][bnr + 8][bc4 + 1], pb1.y);
            put(&Bs[buf][0][bnr + 8][bc4 + 2], &Bs[buf][1][bnr + 8][bc4 + 2], pb1.z);
            put(&Bs[buf][0][bnr + 8][bc4 + 3], &Bs[buf][1][bnr + 8][bc4 + 3], pb1.w);
        }
    };

    auto COMPUTE = [&](int buf) {
        #pragma unroll
        for (int ks = 0; ks < 2; ks++) {
            int kk = ks * 8 + qk;
            uint32_t afh[2][4], afl[2][4];
            #pragma unroll
            for (int mt = 0; mt < 2; mt++) {
                int r = wm + mt * 16 + qrow;
                afh[mt][0] = __float_as_uint(As[buf][0][r][kk]);
                afh[mt][1] = __float_as_uint(As[buf][0][r + 8][kk]);
                afh[mt][2] = __float_as_uint(As[buf][0][r][kk + 4]);
                afh[mt][3] = __float_as_uint(As[buf][0][r + 8][kk + 4]);
                afl[mt][0] = __float_as_uint(As[buf][1][r][kk]);
                afl[mt][1] = __float_as_uint(As[buf][1][r + 8][kk]);
                afl[mt][2] = __float_as_uint(As[buf][1][r][kk + 4]);
                afl[mt][3] = __float_as_uint(As[buf][1][r + 8][kk + 4]);
            }
            uint32_t bfh[4][2], bfl[4][2];
            #pragma unroll
            for (int nt = 0; nt < 4; nt++) {
                int cn = wn + nt * 8 + qrow;
                bfh[nt][0] = __float_as_uint(Bs[buf][0][kk][cn]);
                bfh[nt][1] = __float_as_uint(Bs[buf][0][kk + 4][cn]);
                bfl[nt][0] = __float_as_uint(Bs[buf][1][kk][cn]);
                bfl[nt][1] = __float_as_uint(Bs[buf][1][kk + 4][cn]);
            }
            #pragma unroll
            for (int mt = 0; mt < 2; mt++)
                #pragma unroll
                for (int nt = 0; nt < 4; nt++) {
                    mma8(acc[mt][nt], afh[mt], bfl[nt]);
                    mma8(acc[mt][nt], afl[mt], bfh[nt]);
                    mma8(acc[mt][nt], afh[mt], bfh[nt]);
                }
        }
    };

    int KT = K >> 4;
    LDG(0);
    STS(0);
    __syncthreads();
    for (int kt = 0; kt < KT; kt++) {
        int cur = kt & 1;
        bool more = (kt + 1) < KT;
        if (more) LDG((kt + 1) * 16);
        COMPUTE(cur);
        if (more) {
            __syncthreads();
            STS(cur ^ 1);
            __syncthreads();
        }
    }

    #pragma unroll
    for (int mt = 0; mt < 2; mt++) {
        #pragma unroll
        for (int half = 0; half < 2; half++) {
            int m = m0 + wm + mt * 16 + qrow + half * 8;
            if (m >= M) continue;
            long crow = (long)m * ldc;
            #pragma unroll
            for (int nt = 0; nt < 4; nt++) {
                int col = n0 + wn + nt * 8 + 2 * qk;
                float v0 = alpha * acc[mt][nt][half * 2 + 0];
                float v1 = alpha * acc[mt][nt][half * 2 + 1];
                float2* cp = (float2*)(C + crow + col);
                if (addC) {
                    float2 old = *cp;
                    old.x += v0; old.y += v1;
                    *cp = old;
                } else {
                    *cp = make_float2(v0, v1);
                }
            }
        }
    }
}

// ---------------- 3xTF32 GEMM, 128x128 tile (large shapes) ----------------
// 256 threads = 8 warps (2x4), warp tile 64x32. Raw fp32 smem; hi/lo split at
// fragment load. ~55% per-SM tensor util when grid covers the chip.
template<int MODE, bool TRANSB>
__global__ void __launch_bounds__(256, 1) gemm128_k(
    const float* __restrict__ A, const float* __restrict__ B,
    const float* __restrict__ B2, float* __restrict__ C, float* __restrict__ C2,
    int M, int N, int K, int lda, int ldb, int ldc,
    float alpha, int addC, int causal,
    const int* __restrict__ idxBase, const int* __restrict__ MdevBase,
    long sAb, long sAh, long sBb, long sBh, long sCb, long sCh,
    int nH, int hDiv, long eA, long eB, long eC)
{
    const int* idx = nullptr;
    if (MODE == 0) {
        int z = blockIdx.z;
        int b = z / nH, h = z % nH;
        A += (long)b * sAb + (long)h * sAh;
        B += (long)b * sBb + (long)(h / hDiv) * sBh;
        C += (long)b * sCb + (long)h * sCh;
    } else if (MODE == 1) {
        if (blockIdx.z) { B = B2; C = C2; }
    } else if (MODE == 2) {
        int e = blockIdx.z >> 1, which = blockIdx.z & 1;
        M = MdevBase[e];
        idx = idxBase + e * Tt;
        B = (which ? B2 : B) + (long)e * eB;
        C = (which ? C2 : C) + (long)e * eC;
    } else if (MODE == 3) {
        int e = blockIdx.z;
        M = MdevBase[e];
        A += (long)e * eA;
        B += (long)e * eB;
        C += (long)e * eC;
    }
    constexpr bool GATHER = (MODE == 2);

    int m0 = blockIdx.y * 128, n0 = blockIdx.x * 128;
    if (m0 >= M) return;
    if (causal && n0 >= m0 + 128) return;

    __shared__ float As[2][128][20];   // stride 20: conflict-free frag reads
    __shared__ float Bs[2][16][136];   // stride 136 (=8 mod 32): conflict-free

    int tid = threadIdx.x;
    int lane = tid & 31, warp = tid >> 5;
    int wm = (warp >> 2) * 64, wn = (warp & 3) * 32;
    int qrow = lane >> 2, qk = lane & 3;

    int ar_r = tid >> 2;               // 0..63
    int ac4 = (tid & 3) * 4;
    int gr0 = m0 + ar_r, gr1 = gr0 + 64;
    bool av0 = gr0 < M, av1 = gr1 < M;
    long arow0 = 0, arow1 = 0;
    if (av0) arow0 = (long)(GATHER ? idx[gr0] : gr0) * lda;
    if (av1) arow1 = (long)(GATHER ? idx[gr1] : gr1) * lda;

    int bnr, bc4;
    bool bv0, bv1;
    if (TRANSB) {
        bnr = tid >> 2; bc4 = (tid & 3) * 4;       // n-rows bnr, bnr+64
        bv0 = (n0 + bnr) < N; bv1 = (n0 + bnr + 64) < N;
    } else {
        bnr = tid >> 5; bc4 = (tid & 31) * 4;      // k-rows bnr, bnr+8
        bv0 = bv1 = (n0 + bc4) < N;
    }

    float4 pa0, pa1, pb0, pb1;
    const float4 z4 = make_float4(0.f, 0.f, 0.f, 0.f);

    float acc[4][4][4];
    #pragma unroll
    for (int mt = 0; mt < 4; mt++)
        #pragma unroll
        for (int nt = 0; nt < 4; nt++)
            #pragma unroll
            for (int i = 0; i < 4; i++) acc[mt][nt][i] = 0.f;

    auto LDG = [&](int k0) {
        pa0 = av0 ? *(const float4*)(A + arow0 + k0 + ac4) : z4;
        pa1 = av1 ? *(const float4*)(A + arow1 + k0 + ac4) : z4;
        if (TRANSB) {
            pb0 = bv0 ? *(const float4*)(B + (long)(n0 + bnr) * ldb + k0 + bc4) : z4;
            pb1 = bv1 ? *(const float4*)(B + (long)(n0 + bnr + 64) * ldb + k0 + bc4) : z4;
        } else {
            pb0 = bv0 ? *(const float4*)(B + (long)(k0 + bnr) * ldb + n0 + bc4) : z4;
            pb1 = bv1 ? *(const float4*)(B + (long)(k0 + bnr + 8) * ldb + n0 + bc4) : z4;
        }
    };

    auto STS = [&](int buf) {
        *(float4*)&As[buf][ar_r][ac4] = pa0;
        *(float4*)&As[buf][ar_r + 64][ac4] = pa1;
        if (TRANSB) {
            Bs[buf][bc4 + 0][bnr] = pb0.x;
            Bs[buf][bc4 + 1][bnr] = pb0.y;
            Bs[buf][bc4 + 2][bnr] = pb0.z;
            Bs[buf][bc4 + 3][bnr] = pb0.w;
            Bs[buf][bc4 + 0][bnr + 64] = pb1.x;
            Bs[buf][bc4 + 1][bnr + 64] = pb1.y;
            Bs[buf][bc4 + 2][bnr + 64] = pb1.z;
            Bs[buf][bc4 + 3][bnr + 64] = pb1.w;
        } else {
            *(float4*)&Bs[buf][bnr][bc4] = pb0;
            *(float4*)&Bs[buf][bnr + 8][bc4] = pb1;
        }
    };

    auto split = [&](float v, uint32_t& hi, uint32_t& lo) {
        float h = tf32r(v);
        hi = __float_as_uint(h);
        lo = __float_as_uint(tf32r(v - h));
    };

    auto COMPUTE = [&](int buf) {
        #pragma unroll
        for (int ks = 0; ks < 2; ks++) {
            int kk = ks * 8 + qk;
            uint32_t afh[4][4], afl[4][4];
            #pragma unroll
            for (int mt = 0; mt < 4; mt++) {
                int r = wm + mt * 16 + qrow;
                split(As[buf][r][kk],          afh[mt][0], afl[mt][0]);
                split(As[buf][r + 8][kk],      afh[mt][1], afl[mt][1]);
                split(As[buf][r][kk + 4],      afh[mt][2], afl[mt][2]);
                split(As[buf][r + 8][kk + 4],  afh[mt][3], afl[mt][3]);
            }
            uint32_t bfh[4][2], bfl[4][2];
            #pragma unroll
            for (int nt = 0; nt < 4; nt++) {
                int cn = wn + nt * 8 + qrow;
                split(Bs[buf][kk][cn],      bfh[nt][0], bfl[nt][0]);
                split(Bs[buf][kk + 4][cn],  bfh[nt][1], bfl[nt][1]);
            }
            #pragma unroll
            for (int mt = 0; mt < 4; mt++)
                #pragma unroll
                for (int nt = 0; nt < 4; nt++) {
                    mma8(acc[mt][nt], afh[mt], bfl[nt]);
                    mma8(acc[mt][nt], afl[mt], bfh[nt]);
                    mma8(acc[mt][nt], afh[mt], bfh[nt]);
                }
        }
    };

    int KT = K >> 4;
    LDG(0);
    STS(0);
    __syncthreads();
    for (int kt = 0; kt < KT; kt++) {
        int cur = kt & 1;
        bool more = (kt + 1) < KT;
        if (more) LDG((kt + 1) * 16);
        COMPUTE(cur);
        if (more) {
            __syncthreads();
            STS(cur ^ 1);
            __syncthreads();
        }
    }

    #pragma unroll
    for (int mt = 0; mt < 4; mt++) {
        #pragma unroll
        for (int half = 0; half < 2; half++) {
            int m = m0 + wm + mt * 16 + qrow + half * 8;
            if (m >= M) continue;
            long crow = (long)m * ldc;
            #pragma unroll
            for (int nt = 0; nt < 4; nt++) {
                int colg = n0 + wn + nt * 8;
                if (colg >= N) continue;
                int col = colg + 2 * qk;
                float v0 = alpha * acc[mt][nt][half * 2 + 0];
                float v1 = alpha * acc[mt][nt][half * 2 + 1];
                float2* cp = (float2*)(C + crow + col);
                if (addC) {
                    float2 old = *cp;
                    old.x += v0; old.y += v1;
                    *cp = old;
                } else {
                    *cp = make_float2(v0, v1);
                }
            }
        }
    }
}

// ---------------- host side ----------------
extern "C" void kernel_launch(void* const* d_in, const int* in_sizes, int n_in,
                              void* d_out, int out_size) {
    const int*   tok    = (const int*)d_in[0];
    const int*   pos    = (const int*)d_in[1];
    const float* emb    = (const float*)d_in[2];
    const float* attnw  = (const float*)d_in[3];
    const float* wq     = (const float*)d_in[4];
    const float* wk     = (const float*)d_in[5];
    const float* wv     = (const float*)d_in[6];
    const float* qnw    = (const float*)d_in[7];
    const float* knw    = (const float*)d_in[8];
    const float* wo     = (const float*)d_in[9];
    const float* ffnw   = (const float*)d_in[10];
    const float* rw     = (const float*)d_in[11];
    const float* gw     = (const float*)d_in[12];
    const float* uw     = (const float*)d_in[13];
    const float* dw     = (const float*)d_in[14];
    const float* fnw    = (const float*)d_in[15];
    float* out = (float*)d_out;

    float *px, *ph, *pq, *pk, *pv, *po, *pscores, *pgbuf, *pubuf, *pdbuf, *pegate;
    int *peidx, *pecnt, *pslot;
    cudaGetSymbolAddress((void**)&px, g_x);
    cudaGetSymbolAddress((void**)&ph, g_h);
    cudaGetSymbolAddress((void**)&pq, g_q);
    cudaGetSymbolAddress((void**)&pk, g_k);
    cudaGetSymbolAddress((void**)&pv, g_v);
    cudaGetSymbolAddress((void**)&po, g_o);
    cudaGetSymbolAddress((void**)&pscores, g_scores);
    cudaGetSymbolAddress((void**)&pgbuf, g_gbuf);
    cudaGetSymbolAddress((void**)&pubuf, g_ubuf);
    cudaGetSymbolAddress((void**)&pdbuf, g_dbuf);
    cudaGetSymbolAddress((void**)&pegate, g_egate);
    cudaGetSymbolAddress((void**)&peidx, g_eidx);
    cudaGetSymbolAddress((void**)&pecnt, g_ecnt);
    cudaGetSymbolAddress((void**)&pslot, g_slot);

    const long ZL = 0;

    // embed
    embed_k<<<(Tt * Dd) / 256, 256>>>(tok, emb, px);

    for (int l = 0; l < Ll; l++) {
        const float* wq_l = wq + (long)l * Dd * (Hh * HDd);
        const float* wk_l = wk + (long)l * Dd * (KVh * HDd);
        const float* wv_l = wv + (long)l * Dd * (KVh * HDd);
        const float* wo_l = wo + (long)l * (Hh * HDd) * Dd;
        const float* gw_l = gw + (long)l * Ee * Dd * Ff;
        const float* uw_l = uw + (long)l * Ee * Dd * Ff;
        const float* dw_l = dw + (long)l * Ee * Ff * Dd;

        // ---- attention ----
        rmsnorm_k<<<Tt, 256>>>(px, attnw + (long)l * Dd, ph);

        // Q projection (64-tile: grid 512)
        gemm64_k<0,false><<<dim3(16, 32, 1), 128>>>(
            ph, wq_l, nullptr, pq, nullptr,
            Tt, Hh * HDd, Dd, Dd, Hh * HDd, Hh * HDd,
            1.f, 0, 0, nullptr, nullptr,
            ZL, ZL, ZL, ZL, ZL, ZL, 1, 1, ZL, ZL, ZL);

        // K + V fused (64-tile: grid 256)
        gemm64_k<1,false><<<dim3(4, 32, 2), 128>>>(
            ph, wk_l, wv_l, pk, pv,
            Tt, KVh * HDd, Dd, Dd, KVh * HDd, KVh * HDd,
            1.f, 0, 0, nullptr, nullptr,
            ZL, ZL, ZL, ZL, ZL, ZL, 1, 1, ZL, ZL, ZL);

        qknorm_rope_k<<<Tt * Hh, 64>>>(pq, qnw + (long)l * HDd, pos, Hh, Hh * HDd);
        qknorm_rope_k<<<Tt * KVh, 64>>>(pk, knw + (long)l * HDd, pos, KVh, KVh * HDd);

        // scores = Q @ K^T * scale (128-tile, batched, causal skip)
        gemm128_k<0,true><<<dim3(8, 8, Bz * Hh), 256>>>(
            pq, pk, nullptr, pscores, nullptr,
            Ss, Ss, HDd, Hh * HDd, KVh * HDd, Ss,
            0.125f, 0, 1, nullptr, nullptr,
            (long)Ss * Hh * HDd, (long)HDd,
            (long)Ss * KVh * HDd, (long)HDd,
            (long)Hh * Ss * Ss, (long)Ss * Ss,
            Hh, Hh / KVh, ZL, ZL, ZL);

        softmax_k<<<Bz * Hh * Ss, 256>>>(pscores);

        // O = P @ V (64-tile: N=64)
        gemm64_k<0,false><<<dim3(1, 16, Bz * Hh), 128>>>(
            pscores, pv, nullptr, po, nullptr,
            Ss, HDd, Ss, Ss, KVh * HDd, Hh * HDd,
            1.f, 0, 0, nullptr, nullptr,
            (long)Hh * Ss * Ss, (long)Ss * Ss,
            (long)Ss * KVh * HDd, (long)HDd,
            (long)Ss * Hh * HDd, (long)HDd,
            Hh, Hh / KVh, ZL, ZL, ZL);

        // x += O @ wo (64-tile: grid 512)
        gemm64_k<0,false><<<dim3(16, 32, 1), 128>>>(
            po, wo_l, nullptr, px, nullptr,
            Tt, Dd, Hh * HDd, Hh * HDd, Dd, Dd,
            1.f, 1, 0, nullptr, nullptr,
            ZL, ZL, ZL, ZL, ZL, ZL, 1, 1, ZL, ZL, ZL);

        // ---- MoE ----
        rmsnorm_k<<<Tt, 256>>>(px, ffnw + (long)l * Dd, ph);
        zero_cnt_k<<<1, 32>>>(pecnt);
        router_k<<<Tt, 256>>>(ph, rw + (long)l * Dd * Ee, pecnt, peidx, pegate, pslot);

        // all experts' gate+up in ONE launch (128-tile): z = e*2 + which
        gemm128_k<2,false><<<dim3(8, 16, 2 * Ee), 256>>>(
            ph, gw_l, uw_l, pgbuf, pubuf,
            Tt, Ff, Dd, Dd, Ff, Ff,
            1.f, 0, 0, peidx, pecnt,
            ZL, ZL, ZL, ZL, ZL, ZL, 1, 1,
            ZL, (long)Dd * Ff, (long)Tt * Ff);

        // fused silu*up over all experts
        silu_all_k<<<(int)(((long)Ee * Tt * Ff) / 256), 256>>>(pgbuf, pubuf, pecnt);

        // all experts' down-proj in ONE launch (128-tile) -> per-slot buffer
        gemm128_k<3,false><<<dim3(8, 16, Ee), 256>>>(
            pgbuf, dw_l, nullptr, pdbuf, nullptr,
            Tt, Dd, Ff, Ff, Dd, Dd,
            1.f, 0, 0, nullptr, pecnt,
            ZL, ZL, ZL, ZL, ZL, ZL, 1, 1,
            (long)Tt * Ff, (long)Ff * Dd, (long)Tt * Dd);

        // deterministic combine: x += gate0*y0 + gate1*y1
        combine_k<<<(Tt * Dd) / 256, 256>>>(px, pdbuf, pslot, pegate);
    }

    // final norm + tied lm_head (128-tile: grid 250x16 = 4000)
    rmsnorm_k<<<Tt, 256>>>(px, fnw, ph);
    gemm128_k<0,true><<<dim3(Vv / 128, Tt / 128, 1), 256>>>(
        ph, emb, nullptr, out, nullptr,
        Tt, Vv, Dd, Dd, Dd, Vv,
        1.f, 0, 0, nullptr, nullptr,
        ZL, ZL, ZL, ZL, ZL, ZL, 1, 1, ZL, ZL, ZL);
}

// round 11
// speedup vs baseline: 1.8953x; 1.0170x over previous
#include <cuda_runtime.h>
#include <cuda_bf16.h>
#include <math.h>
#include <stdint.h>

// ---------------- model dims ----------------
#define Bz   2
#define Ss   1024
#define Tt   (Bz*Ss)        // 2048 tokens
#define Dd   1024
#define Hh   16
#define KVh  4
#define HDd  64
#define Ll   4
#define Ee   8
#define Ff   1024
#define Vv   32000

// ---------------- scratch (device globals; no allocation) ----------------
__device__ float g_x[Tt*Dd];
__device__ float g_h[Tt*Dd];
__device__ float g_q[Tt*Hh*HDd];
__device__ float g_k[Tt*KVh*HDd];
__device__ float g_v[Tt*KVh*HDd];
__device__ float g_scores[(size_t)Bz*Hh*Ss*Ss];   // 134 MB
__device__ float g_o[Tt*Hh*HDd];
__device__ float g_gbuf[(size_t)Ee*Tt*Ff];        // 67 MB per-expert gate
__device__ float g_ubuf[(size_t)Ee*Tt*Ff];        // 67 MB per-expert up
__device__ float g_dbuf[(size_t)Ee*Tt*Dd];        // 67 MB per-slot down output
__device__ int   g_eidx[Ee*Tt];
__device__ float g_egate[Ee*Tt];
__device__ int   g_ecnt[Ee];
__device__ int   g_slot[2*Tt];                    // token -> its two (e*Tt+pos) slots

// ---------------- helpers ----------------
__device__ __forceinline__ float tf32r(float x) {
    uint32_t u;
    asm("cvt.rna.tf32.f32 %0, %1;" : "=r"(u) : "f"(x));
    return __uint_as_float(u);
}

__device__ __forceinline__ void mma8(float* c, const uint32_t* a, const uint32_t* b) {
    asm volatile("mma.sync.aligned.m16n8k8.row.col.f32.tf32.tf32.f32 "
                 "{%0,%1,%2,%3}, {%4,%5,%6,%7}, {%8,%9}, {%0,%1,%2,%3};"
                 : "+f"(c[0]), "+f"(c[1]), "+f"(c[2]), "+f"(c[3])
                 : "r"(a[0]), "r"(a[1]), "r"(a[2]), "r"(a[3]),
                   "r"(b[0]), "r"(b[1]));
}

__device__ __forceinline__ float blockReduceSum256(float v) {
    __shared__ float sh[32];
    int lane = threadIdx.x & 31, wid = threadIdx.x >> 5;
    #pragma unroll
    for (int o = 16; o; o >>= 1) v += __shfl_xor_sync(0xffffffffu, v, o);
    if (lane == 0) sh[wid] = v;
    __syncthreads();
    int nw = (blockDim.x + 31) >> 5;
    float r = (threadIdx.x < nw) ? sh[threadIdx.x] : 0.f;
    if (wid == 0) {
        #pragma unroll
        for (int o = 16; o; o >>= 1) r += __shfl_xor_sync(0xffffffffu, r, o);
        if (lane == 0) sh[0] = r;
    }
    __syncthreads();
    float out = sh[0];
    __syncthreads();
    return out;
}

__device__ __forceinline__ float blockReduceMax256(float v) {
    __shared__ float sh[32];
    int lane = threadIdx.x & 31, wid = threadIdx.x >> 5;
    #pragma unroll
    for (int o = 16; o; o >>= 1) v = fmaxf(v, __shfl_xor_sync(0xffffffffu, v, o));
    if (lane == 0) sh[wid] = v;
    __syncthreads();
    int nw = (blockDim.x + 31) >> 5;
    float r = (threadIdx.x < nw) ? sh[threadIdx.x] : -INFINITY;
    if (wid == 0) {
        #pragma unroll
        for (int o = 16; o; o >>= 1) r = fmaxf(r, __shfl_xor_sync(0xffffffffu, r, o));
        if (lane == 0) sh[0] = r;
    }
    __syncthreads();
    float out = sh[0];
    __syncthreads();
    return out;
}

// ---------------- elementwise kernels ----------------
__global__ void embed_k(const int* __restrict__ tok, const float* __restrict__ emb,
                        float* __restrict__ x) {
    int i = blockIdx.x * 256 + threadIdx.x;
    int t = i / Dd, d = i % Dd;
    x[i] = emb[(long)tok[t] * Dd + d];
}

__global__ void rmsnorm_k(const float* __restrict__ x, const float* __restrict__ w,
                          float* __restrict__ out) {
    int row = blockIdx.x;
    const float* xr = x + (long)row * Dd;
    float* orow = out + (long)row * Dd;
    float ss = 0.f;
    #pragma unroll
    for (int i = 0; i < 4; i++) {
        float v = xr[threadIdx.x + i * 256];
        ss += v * v;
    }
    float tot = blockReduceSum256(ss);
    float scale = rsqrtf(tot / (float)Dd + 1e-6f);
    #pragma unroll
    for (int i = 0; i < 4; i++) {
        int d = threadIdx.x + i * 256;
        orow[d] = xr[d] * scale * w[d];
    }
}

// per-head RMSNorm + RoPE, in place. block = 64 threads = one (token, head)
__global__ void qknorm_rope_k(float* __restrict__ qk, const float* __restrict__ nw,
                              const int* __restrict__ pos, int nHeads, int ld) {
    int bid = blockIdx.x;
    int t = bid / nHeads, hh = bid % nHeads;
    float* v = qk + (long)t * ld + hh * HDd;
    int d = threadIdx.x;
    float x = v[d];
    float ss = x * x;
    #pragma unroll
    for (int o = 16; o; o >>= 1) ss += __shfl_xor_sync(0xffffffffu, ss, o);
    __shared__ float s2[2];
    if ((d & 31) == 0) s2[d >> 5] = ss;
    __syncthreads();
    float tot = s2[0] + s2[1];
    float scale = rsqrtf(tot / 64.f + 1e-6f);
    float xn = x * scale * nw[d];
    __shared__ float sh[64];
    sh[d] = xn;
    __syncthreads();
    int p = pos[t];
    int fi = d & 31;
    float inv = powf(1e6f, -(float)fi / 32.f);
    float ang = (float)p * inv;
    float c = cosf(ang), s = sinf(ang);
    float other = (d < 32) ? sh[d + 32] : sh[d - 32];
    float rot = (d < 32) ? -other : other;
    v[d] = xn * c + rot * s;
}

// causal softmax over scores rows; zero-fills j>q
__global__ void softmax_k(float* __restrict__ scores) {
    long row = blockIdx.x;                 // B*H*S rows
    int q = (int)(row % Ss);
    float* p = scores + row * Ss;
    int valid = q + 1;
    float mx = -INFINITY;
    for (int j = threadIdx.x; j < valid; j += 256) mx = fmaxf(mx, p[j]);
    mx = blockReduceMax256(mx);
    float sum = 0.f;
    for (int j = threadIdx.x; j < valid; j += 256) {
        float e = expf(p[j] - mx);
        p[j] = e;
        sum += e;
    }
    sum = blockReduceSum256(sum);
    float inv = 1.f / sum;
    for (int j = threadIdx.x; j < valid; j += 256) p[j] *= inv;
    for (int j = valid + threadIdx.x; j < Ss; j += 256) p[j] = 0.f;
}

__global__ void zero_cnt_k(int* c) { if (threadIdx.x < Ee) c[threadIdx.x] = 0; }

// router: logits = h @ rw [D,E]; top-2; normalize; fill expert lists + token slots
__global__ void router_k(const float* __restrict__ h, const float* __restrict__ rw,
                         int* __restrict__ ecnt, int* __restrict__ eidx,
                         float* __restrict__ egate, int* __restrict__ slot) {
    int t = blockIdx.x;
    int lane = threadIdx.x & 31, w = threadIdx.x >> 5;   // warp per expert
    const float* hr = h + (long)t * Dd;
    float s = 0.f;
    for (int d = lane; d < Dd; d += 32) s += hr[d] * rw[(long)d * Ee + w];
    #pragma unroll
    for (int o = 16; o; o >>= 1) s += __shfl_xor_sync(0xffffffffu, s, o);
    __shared__ float lg[Ee];
    if (lane == 0) lg[w] = s;
    __syncthreads();
    if (threadIdx.x == 0) {
        int a = 0;
        #pragma unroll
        for (int i = 1; i < Ee; i++) if (lg[i] > lg[a]) a = i;
        int b = (a == 0) ? 1 : 0;
        #pragma unroll
        for (int i = 0; i < Ee; i++) if (i != a && lg[i] > lg[b]) b = i;
        float wa = 1.f / (1.f + expf(lg[b] - lg[a]));
        float wb = 1.f - wa;
        int pa = atomicAdd(&ecnt[a], 1);
        eidx[a * Tt + pa] = t; egate[a * Tt + pa] = wa;
        int pb = atomicAdd(&ecnt[b], 1);
        eidx[b * Tt + pb] = t; egate[b * Tt + pb] = wb;
        slot[2 * t + 0] = a * Tt + pa;
        slot[2 * t + 1] = b * Tt + pb;
    }
}

// fused silu*up over ALL experts' staging regions (early-exit on count)
__global__ void silu_all_k(float* __restrict__ g, const float* __restrict__ u,
                           const int* __restrict__ cnt) {
    long i = (long)blockIdx.x * 256 + threadIdx.x;
    int e = (int)(i / ((long)Tt * Ff));
    long rem = i % ((long)Tt * Ff);
    if ((int)(rem / Ff) >= cnt[e]) return;
    float x = g[i];
    g[i] = (x / (1.f + expf(-x))) * u[i];
}

// deterministic combine: x[t] += gate0*dbuf[slot0] + gate1*dbuf[slot1]
__global__ void combine_k(float* __restrict__ x, const float* __restrict__ dbuf,
                          const int* __restrict__ slot, const float* __restrict__ eg) {
    long i = (long)blockIdx.x * 256 + threadIdx.x;   // Tt*Dd
    int t = (int)(i / Dd), d = (int)(i % Dd);
    int s0 = slot[2 * t], s1 = slot[2 * t + 1];
    x[i] += eg[s0] * dbuf[(long)s0 * Dd + d] + eg[s1] * dbuf[(long)s1 * Dd + d];
}

// ========== MODE semantics (both GEMM kernels) ==========
// MODE 0: batched heads via z (b=z/nH, h=z%nH; strides sAb/sAh/...)
// MODE 1: dual output; z=0 -> (B,C), z=1 -> (B2,C2)
// MODE 2: expert dual + gather: z -> (e=z>>1, which=z&1); M=Mdev[e];
//         A row m -> A[idx[m]]; B/C from (which? B2/C2 : B/C) + e*stride
// MODE 3: expert single: z=e; M=Mdev[e]; A/B/C += e*stride

// ---------------- 3xTF32 GEMM, 64x64 tile (small/batched shapes) ----------------
// 128 threads = 4 warps (2x2), warp tile 32x32. Raw fp32 smem; hi/lo split at
// fragment load (halves LDS traffic vs hi/lo-in-smem). N%64==0, K%16==0.
template<int MODE, bool TRANSB>
__global__ void __launch_bounds__(128) gemm64_k(
    const float* __restrict__ A, const float* __restrict__ B,
    const float* __restrict__ B2, float* __restrict__ C, float* __restrict__ C2,
    int M, int N, int K, int lda, int ldb, int ldc,
    float alpha, int addC, int causal,
    const int* __restrict__ idxBase, const int* __restrict__ MdevBase,
    long sAb, long sAh, long sBb, long sBh, long sCb, long sCh,
    int nH, int hDiv, long eA, long eB, long eC)
{
    const int* idx = nullptr;
    if (MODE == 0) {
        int z = blockIdx.z;
        int b = z / nH, h = z % nH;
        A += (long)b * sAb + (long)h * sAh;
        B += (long)b * sBb + (long)(h / hDiv) * sBh;
        C += (long)b * sCb + (long)h * sCh;
    } else if (MODE == 1) {
        if (blockIdx.z) { B = B2; C = C2; }
    } else if (MODE == 2) {
        int e = blockIdx.z >> 1, which = blockIdx.z & 1;
        M = MdevBase[e];
        idx = idxBase + e * Tt;
        B = (which ? B2 : B) + (long)e * eB;
        C = (which ? C2 : C) + (long)e * eC;
    } else {
        int e = blockIdx.z;
        M = MdevBase[e];
        A += (long)e * eA;
        B += (long)e * eB;
        C += (long)e * eC;
    }
    constexpr bool GATHER = (MODE == 2);

    int m0 = blockIdx.y * 64, n0 = blockIdx.x * 64;
    if (m0 >= M) return;
    if (causal && n0 >= m0 + 64) return;

    __shared__ float As[2][64][20];   // raw fp32; stride 20 conflict-free
    __shared__ float Bs[2][16][72];   // raw fp32; stride 72 conflict-free

    int tid = threadIdx.x;
    int lane = tid & 31, warp = tid >> 5;
    int wm = (warp >> 1) * 32, wn = (warp & 1) * 32;
    int qrow = lane >> 2, qk = lane & 3;

    int ar_r = tid >> 2;               // 0..31
    int ac4 = (tid & 3) * 4;
    int gr0 = m0 + ar_r, gr1 = gr0 + 32;
    bool av0 = gr0 < M, av1 = gr1 < M;
    long arow0 = 0, arow1 = 0;
    if (av0) arow0 = (long)(GATHER ? idx[gr0] : gr0) * lda;
    if (av1) arow1 = (long)(GATHER ? idx[gr1] : gr1) * lda;

    int bnr, bc4;
    if (TRANSB) { bnr = tid >> 2; bc4 = (tid & 3) * 4; }
    else        { bnr = tid >> 4; bc4 = (tid & 15) * 4; }

    float4 pa0, pa1, pb0, pb1;
    const float4 z4 = make_float4(0.f, 0.f, 0.f, 0.f);

    float acc[2][4][4];
    #pragma unroll
    for (int mt = 0; mt < 2; mt++)
        #pragma unroll
        for (int nt = 0; nt < 4; nt++)
            #pragma unroll
            for (int i = 0; i < 4; i++) acc[mt][nt][i] = 0.f;

    auto LDG = [&](int k0) {
        pa0 = av0 ? *(const float4*)(A + arow0 + k0 + ac4) : z4;
        pa1 = av1 ? *(const float4*)(A + arow1 + k0 + ac4) : z4;
        if (TRANSB) {
            pb0 = *(const float4*)(B + (long)(n0 + bnr) * ldb + k0 + bc4);
            pb1 = *(const float4*)(B + (long)(n0 + bnr + 32) * ldb + k0 + bc4);
        } else {
            pb0 = *(const float4*)(B + (long)(k0 + bnr) * ldb + n0 + bc4);
            pb1 = *(const float4*)(B + (long)(k0 + bnr + 8) * ldb + n0 + bc4);
        }
    };

    auto STS = [&](int buf) {
        *(float4*)&As[buf][ar_r][ac4] = pa0;
        *(float4*)&As[buf][ar_r + 32][ac4] = pa1;
        if (TRANSB) {
            Bs[buf][bc4 + 0][bnr] = pb0.x;
            Bs[buf][bc4 + 1][bnr] = pb0.y;
            Bs[buf][bc4 + 2][bnr] = pb0.z;
            Bs[buf][bc4 + 3][bnr] = pb0.w;
            Bs[buf][bc4 + 0][bnr + 32] = pb1.x;
            Bs[buf][bc4 + 1][bnr + 32] = pb1.y;
            Bs[buf][bc4 + 2][bnr + 32] = pb1.z;
            Bs[buf][bc4 + 3][bnr + 32] = pb1.w;
        } else {
            *(float4*)&Bs[buf][bnr][bc4] = pb0;
            *(float4*)&Bs[buf][bnr + 8][bc4] = pb1;
        }
    };

    auto split = [&](float v, uint32_t& hi, uint32_t& lo) {
        float h = tf32r(v);
        hi = __float_as_uint(h);
        lo = __float_as_uint(tf32r(v - h));
    };

    auto COMPUTE = [&](int buf) {
        #pragma unroll
        for (int ks = 0; ks < 2; ks++) {
            int kk = ks * 8 + qk;
            uint32_t afh[2][4], afl[2][4];
            #pragma unroll
            for (int mt = 0; mt < 2; mt++) {
                int r = wm + mt * 16 + qrow;
                split(As[buf][r][kk],          afh[mt][0], afl[mt][0]);
                split(As[buf][r + 8][kk],      afh[mt][1], afl[mt][1]);
                split(As[buf][r][kk + 4],      afh[mt][2], afl[mt][2]);
                split(As[buf][r + 8][kk + 4],  afh[mt][3], afl[mt][3]);
            }
            uint32_t bfh[4][2], bfl[4][2];
            #pragma unroll
            for (int nt = 0; nt < 4; nt++) {
                int cn = wn + nt * 8 + qrow;
                split(Bs[buf][kk][cn],      bfh[nt][0], bfl[nt][0]);
                split(Bs[buf][kk + 4][cn],  bfh[nt][1], bfl[nt][1]);
            }
            #pragma unroll
            for (int mt = 0; mt < 2; mt++)
                #pragma unroll
                for (int nt = 0; nt < 4; nt++) {
                    mma8(acc[mt][nt], afh[mt], bfl[nt]);
                    mma8(acc[mt][nt], afl[mt], bfh[nt]);
                    mma8(acc[mt][nt], afh[mt], bfh[nt]);
                }
        }
    };

    int KT = K >> 4;
    LDG(0);
    STS(0);
    __syncthreads();
    for (int kt = 0; kt < KT; kt++) {
        int cur = kt & 1;
        bool more = (kt + 1) < KT;
        if (more) LDG((kt + 1) * 16);
        COMPUTE(cur);
        if (more) {
            __syncthreads();
            STS(cur ^ 1);
            __syncthreads();
        }
    }

    #pragma unroll
    for (int mt = 0; mt < 2; mt++) {
        #pragma unroll
        for (int half = 0; half < 2; half++) {
            int m = m0 + wm + mt * 16 + qrow + half * 8;
            if (m >= M) continue;
            long crow = (long)m * ldc;
            #pragma unroll
            for (int nt = 0; nt < 4; nt++) {
                int col = n0 + wn + nt * 8 + 2 * qk;
                float v0 = alpha * acc[mt][nt][half * 2 + 0];
                float v1 = alpha * acc[mt][nt][half * 2 + 1];
                float2* cp = (float2*)(C + crow + col);
                if (addC) {
                    float2 old = *cp;
                    old.x += v0; old.y += v1;
                    *cp = old;
                } else {
                    *cp = make_float2(v0, v1);
                }
            }
        }
    }
}

// ---------------- 3xTF32 GEMM, 128x128 tile (large shapes) ----------------
// 256 threads = 8 warps (2x4), warp tile 64x32. Raw fp32 smem; hi/lo split at
// fragment load. launch_bounds(256,2): 128-reg budget -> 2 blocks/SM for
// latency hiding (spills land on cold LDG staging, not accumulators).
template<int MODE, bool TRANSB>
__global__ void __launch_bounds__(256, 2) gemm128_k(
    const float* __restrict__ A, const float* __restrict__ B,
    const float* __restrict__ B2, float* __restrict__ C, float* __restrict__ C2,
    int M, int N, int K, int lda, int ldb, int ldc,
    float alpha, int addC, int causal,
    const int* __restrict__ idxBase, const int* __restrict__ MdevBase,
    long sAb, long sAh, long sBb, long sBh, long sCb, long sCh,
    int nH, int hDiv, long eA, long eB, long eC)
{
    const int* idx = nullptr;
    if (MODE == 0) {
        int z = blockIdx.z;
        int b = z / nH, h = z % nH;
        A += (long)b * sAb + (long)h * sAh;
        B += (long)b * sBb + (long)(h / hDiv) * sBh;
        C += (long)b * sCb + (long)h * sCh;
    } else if (MODE == 1) {
        if (blockIdx.z) { B = B2; C = C2; }
    } else if (MODE == 2) {
        int e = blockIdx.z >> 1, which = blockIdx.z & 1;
        M = MdevBase[e];
        idx = idxBase + e * Tt;
        B = (which ? B2 : B) + (long)e * eB;
        C = (which ? C2 : C) + (long)e * eC;
    } else if (MODE == 3) {
        int e = blockIdx.z;
        M = MdevBase[e];
        A += (long)e * eA;
        B += (long)e * eB;
        C += (long)e * eC;
    }
    constexpr bool GATHER = (MODE == 2);

    int m0 = blockIdx.y * 128, n0 = blockIdx.x * 128;
    if (m0 >= M) return;
    if (causal && n0 >= m0 + 128) return;

    __shared__ float As[2][128][20];   // stride 20: conflict-free frag reads
    __shared__ float Bs[2][16][136];   // stride 136 (=8 mod 32): conflict-free

    int tid = threadIdx.x;
    int lane = tid & 31, warp = tid >> 5;
    int wm = (warp >> 2) * 64, wn = (warp & 3) * 32;
    int qrow = lane >> 2, qk = lane & 3;

    int ar_r = tid >> 2;               // 0..63
    int ac4 = (tid & 3) * 4;
    int gr0 = m0 + ar_r, gr1 = gr0 + 64;
    bool av0 = gr0 < M, av1 = gr1 < M;
    long arow0 = 0, arow1 = 0;
    if (av0) arow0 = (long)(GATHER ? idx[gr0] : gr0) * lda;
    if (av1) arow1 = (long)(GATHER ? idx[gr1] : gr1) * lda;

    int bnr, bc4;
    bool bv0, bv1;
    if (TRANSB) {
        bnr = tid >> 2; bc4 = (tid & 3) * 4;       // n-rows bnr, bnr+64
        bv0 = (n0 + bnr) < N; bv1 = (n0 + bnr + 64) < N;
    } else {
        bnr = tid >> 5; bc4 = (tid & 31) * 4;      // k-rows bnr, bnr+8
        bv0 = bv1 = (n0 + bc4) < N;
    }

    float4 pa0, pa1, pb0, pb1;
    const float4 z4 = make_float4(0.f, 0.f, 0.f, 0.f);

    float acc[4][4][4];
    #pragma unroll
    for (int mt = 0; mt < 4; mt++)
        #pragma unroll
        for (int nt = 0; nt < 4; nt++)
            #pragma unroll
            for (int i = 0; i < 4; i++) acc[mt][nt][i] = 0.f;

    auto LDG = [&](int k0) {
        pa0 = av0 ? *(const float4*)(A + arow0 + k0 + ac4) : z4;
        pa1 = av1 ? *(const float4*)(A + arow1 + k0 + ac4) : z4;
        if (TRANSB) {
            pb0 = bv0 ? *(const float4*)(B + (long)(n0 + bnr) * ldb + k0 + bc4) : z4;
            pb1 = bv1 ? *(const float4*)(B + (long)(n0 + bnr + 64) * ldb + k0 + bc4) : z4;
        } else {
            pb0 = bv0 ? *(const float4*)(B + (long)(k0 + bnr) * ldb + n0 + bc4) : z4;
            pb1 = bv1 ? *(const float4*)(B + (long)(k0 + bnr + 8) * ldb + n0 + bc4) : z4;
        }
    };

    auto STS = [&](int buf) {
        *(float4*)&As[buf][ar_r][ac4] = pa0;
        *(float4*)&As[buf][ar_r + 64][ac4] = pa1;
        if (TRANSB) {
            Bs[buf][bc4 + 0][bnr] = pb0.x;
            Bs[buf][bc4 + 1][bnr] = pb0.y;
            Bs[buf][bc4 + 2][bnr] = pb0.z;
            Bs[buf][bc4 + 3][bnr] = pb0.w;
            Bs[buf][bc4 + 0][bnr + 64] = pb1.x;
            Bs[buf][bc4 + 1][bnr + 64] = pb1.y;
            Bs[buf][bc4 + 2][bnr + 64] = pb1.z;
            Bs[buf][bc4 + 3][bnr + 64] = pb1.w;
        } else {
            *(float4*)&Bs[buf][bnr][bc4] = pb0;
            *(float4*)&Bs[buf][bnr + 8][bc4] = pb1;
        }
    };

    auto split = [&](float v, uint32_t& hi, uint32_t& lo) {
        float h = tf32r(v);
        hi = __float_as_uint(h);
        lo = __float_as_uint(tf32r(v - h));
    };

    auto COMPUTE = [&](int buf) {
        #pragma unroll
        for (int ks = 0; ks < 2; ks++) {
            int kk = ks * 8 + qk;
            uint32_t afh[4][4], afl[4][4];
            #pragma unroll
            for (int mt = 0; mt < 4; mt++) {
                int r = wm + mt * 16 + qrow;
                split(As[buf][r][kk],          afh[mt][0], afl[mt][0]);
                split(As[buf][r + 8][kk],      afh[mt][1], afl[mt][1]);
                split(As[buf][r][kk + 4],      afh[mt][2], afl[mt][2]);
                split(As[buf][r + 8][kk + 4],  afh[mt][3], afl[mt][3]);
            }
            uint32_t bfh[4][2], bfl[4][2];
            #pragma unroll
            for (int nt = 0; nt < 4; nt++) {
                int cn = wn + nt * 8 + qrow;
                split(Bs[buf][kk][cn],      bfh[nt][0], bfl[nt][0]);
                split(Bs[buf][kk + 4][cn],  bfh[nt][1], bfl[nt][1]);
            }
            #pragma unroll
            for (int mt = 0; mt < 4; mt++)
                #pragma unroll
                for (int nt = 0; nt < 4; nt++) {
                    mma8(acc[mt][nt], afh[mt], bfl[nt]);
                    mma8(acc[mt][nt], afl[mt], bfh[nt]);
                    mma8(acc[mt][nt], afh[mt], bfh[nt]);
                }
        }
    };

    int KT = K >> 4;
    LDG(0);
    STS(0);
    __syncthreads();
    for (int kt = 0; kt < KT; kt++) {
        int cur = kt & 1;
        bool more = (kt + 1) < KT;
        if (more) LDG((kt + 1) * 16);
        COMPUTE(cur);
        if (more) {
            __syncthreads();
            STS(cur ^ 1);
            __syncthreads();
        }
    }

    #pragma unroll
    for (int mt = 0; mt < 4; mt++) {
        #pragma unroll
        for (int half = 0; half < 2; half++) {
            int m = m0 + wm + mt * 16 + qrow + half * 8;
            if (m >= M) continue;
            long crow = (long)m * ldc;
            #pragma unroll
            for (int nt = 0; nt < 4; nt++) {
                int colg = n0 + wn + nt * 8;
                if (colg >= N) continue;
                int col = colg + 2 * qk;
                float v0 = alpha * acc[mt][nt][half * 2 + 0];
                float v1 = alpha * acc[mt][nt][half * 2 + 1];
                float2* cp = (float2*)(C + crow + col);
                if (addC) {
                    float2 old = *cp;
                    old.x += v0; old.y += v1;
                    *cp = old;
                } else {
                    *cp = make_float2(v0, v1);
                }
            }
        }
    }
}

// ---------------- host side ----------------
extern "C" void kernel_launch(void* const* d_in, const int* in_sizes, int n_in,
                              void* d_out, int out_size) {
    const int*   tok    = (const int*)d_in[0];
    const int*   pos    = (const int*)d_in[1];
    const float* emb    = (const float*)d_in[2];
    const float* attnw  = (const float*)d_in[3];
    const float* wq     = (const float*)d_in[4];
    const float* wk     = (const float*)d_in[5];
    const float* wv     = (const float*)d_in[6];
    const float* qnw    = (const float*)d_in[7];
    const float* knw    = (const float*)d_in[8];
    const float* wo     = (const float*)d_in[9];
    const float* ffnw   = (const float*)d_in[10];
    const float* rw     = (const float*)d_in[11];
    const float* gw     = (const float*)d_in[12];
    const float* uw     = (const float*)d_in[13];
    const float* dw     = (const float*)d_in[14];
    const float* fnw    = (const float*)d_in[15];
    float* out = (float*)d_out;

    float *px, *ph, *pq, *pk, *pv, *po, *pscores, *pgbuf, *pubuf, *pdbuf, *pegate;
    int *peidx, *pecnt, *pslot;
    cudaGetSymbolAddress((void**)&px, g_x);
    cudaGetSymbolAddress((void**)&ph, g_h);
    cudaGetSymbolAddress((void**)&pq, g_q);
    cudaGetSymbolAddress((void**)&pk, g_k);
    cudaGetSymbolAddress((void**)&pv, g_v);
    cudaGetSymbolAddress((void**)&po, g_o);
    cudaGetSymbolAddress((void**)&pscores, g_scores);
    cudaGetSymbolAddress((void**)&pgbuf, g_gbuf);
    cudaGetSymbolAddress((void**)&pubuf, g_ubuf);
    cudaGetSymbolAddress((void**)&pdbuf, g_dbuf);
    cudaGetSymbolAddress((void**)&pegate, g_egate);
    cudaGetSymbolAddress((void**)&peidx, g_eidx);
    cudaGetSymbolAddress((void**)&pecnt, g_ecnt);
    cudaGetSymbolAddress((void**)&pslot, g_slot);

    const long ZL = 0;

    // embed
    embed_k<<<(Tt * Dd) / 256, 256>>>(tok, emb, px);

    for (int l = 0; l < Ll; l++) {
        const float* wq_l = wq + (long)l * Dd * (Hh * HDd);
        const float* wk_l = wk + (long)l * Dd * (KVh * HDd);
        const float* wv_l = wv + (long)l * Dd * (KVh * HDd);
        const float* wo_l = wo + (long)l * (Hh * HDd) * Dd;
        const float* gw_l = gw + (long)l * Ee * Dd * Ff;
        const float* uw_l = uw + (long)l * Ee * Dd * Ff;
        const float* dw_l = dw + (long)l * Ee * Ff * Dd;

        // ---- attention ----
        rmsnorm_k<<<Tt, 256>>>(px, attnw + (long)l * Dd, ph);

        // Q projection (64-tile: grid 512)
        gemm64_k<0,false><<<dim3(16, 32, 1), 128>>>(
            ph, wq_l, nullptr, pq, nullptr,
            Tt, Hh * HDd, Dd, Dd, Hh * HDd, Hh * HDd,
            1.f, 0, 0, nullptr, nullptr,
            ZL, ZL, ZL, ZL, ZL, ZL, 1, 1, ZL, ZL, ZL);

        // K + V fused (64-tile: grid 256)
        gemm64_k<1,false><<<dim3(4, 32, 2), 128>>>(
            ph, wk_l, wv_l, pk, pv,
            Tt, KVh * HDd, Dd, Dd, KVh * HDd, KVh * HDd,
            1.f, 0, 0, nullptr, nullptr,
            ZL, ZL, ZL, ZL, ZL, ZL, 1, 1, ZL, ZL, ZL);

        qknorm_rope_k<<<Tt * Hh, 64>>>(pq, qnw + (long)l * HDd, pos, Hh, Hh * HDd);
        qknorm_rope_k<<<Tt * KVh, 64>>>(pk, knw + (long)l * HDd, pos, KVh, KVh * HDd);

        // scores = Q @ K^T * scale (128-tile, batched, causal skip)
        gemm128_k<0,true><<<dim3(8, 8, Bz * Hh), 256>>>(
            pq, pk, nullptr, pscores, nullptr,
            Ss, Ss, HDd, Hh * HDd, KVh * HDd, Ss,
            0.125f, 0, 1, nullptr, nullptr,
            (long)Ss * Hh * HDd, (long)HDd,
            (long)Ss * KVh * HDd, (long)HDd,
            (long)Hh * Ss * Ss, (long)Ss * Ss,
            Hh, Hh / KVh, ZL, ZL, ZL);

        softmax_k<<<Bz * Hh * Ss, 256>>>(pscores);

        // O = P @ V (64-tile: N=64)
        gemm64_k<0,false><<<dim3(1, 16, Bz * Hh), 128>>>(
            pscores, pv, nullptr, po, nullptr,
            Ss, HDd, Ss, Ss, KVh * HDd, Hh * HDd,
            1.f, 0, 0, nullptr, nullptr,
            (long)Hh * Ss * Ss, (long)Ss * Ss,
            (long)Ss * KVh * HDd, (long)HDd,
            (long)Ss * Hh * HDd, (long)HDd,
            Hh, Hh / KVh, ZL, ZL, ZL);

        // x += O @ wo (64-tile: grid 512)
        gemm64_k<0,false><<<dim3(16, 32, 1), 128>>>(
            po, wo_l, nullptr, px, nullptr,
            Tt, Dd, Hh * HDd, Hh * HDd, Dd, Dd,
            1.f, 1, 0, nullptr, nullptr,
            ZL, ZL, ZL, ZL, ZL, ZL, 1, 1, ZL, ZL, ZL);

        // ---- MoE ----
        rmsnorm_k<<<Tt, 256>>>(px, ffnw + (long)l * Dd, ph);
        zero_cnt_k<<<1, 32>>>(pecnt);
        router_k<<<Tt, 256>>>(ph, rw + (long)l * Dd * Ee, pecnt, peidx, pegate, pslot);

        // all experts' gate+up in ONE launch (128-tile): z = e*2 + which
        gemm128_k<2,false><<<dim3(8, 16, 2 * Ee), 256>>>(
            ph, gw_l, uw_l, pgbuf, pubuf,
            Tt, Ff, Dd, Dd, Ff, Ff,
            1.f, 0, 0, peidx, pecnt,
            ZL, ZL, ZL, ZL, ZL, ZL, 1, 1,
            ZL, (long)Dd * Ff, (long)Tt * Ff);

        // fused silu*up over all experts
        silu_all_k<<<(int)(((long)Ee * Tt * Ff) / 256), 256>>>(pgbuf, pubuf, pecnt);

        // all experts' down-proj in ONE launch (128-tile) -> per-slot buffer
        gemm128_k<3,false><<<dim3(8, 16, Ee), 256>>>(
            pgbuf, dw_l, nullptr, pdbuf, nullptr,
            Tt, Dd, Ff, Ff, Dd, Dd,
            1.f, 0, 0, nullptr, pecnt,
            ZL, ZL, ZL, ZL, ZL, ZL, 1, 1,
            (long)Tt * Ff, (long)Ff * Dd, (long)Tt * Dd);

        // deterministic combine: x += gate0*y0 + gate1*y1
        combine_k<<<(Tt * Dd) / 256, 256>>>(px, pdbuf, pslot, pegate);
    }

    // final norm + tied lm_head (128-tile: grid 250x16 = 4000)
    rmsnorm_k<<<Tt, 256>>>(px, fnw, ph);
    gemm128_k<0,true><<<dim3(Vv / 128, Tt / 128, 1), 256>>>(
        ph, emb, nullptr, out, nullptr,
        Tt, Vv, Dd, Dd, Dd, Vv,
        1.f, 0, 0, nullptr, nullptr,
        ZL, ZL, ZL, ZL, ZL, ZL, 1, 1, ZL, ZL, ZL);
}

// round 13
// speedup vs baseline: 1.9418x; 1.0245x over previous
#include <cuda_runtime.h>
#include <cuda_bf16.h>
#include <math.h>
#include <stdint.h>

// ---------------- model dims ----------------
#define Bz   2
#define Ss   1024
#define Tt   (Bz*Ss)        // 2048 tokens
#define Dd   1024
#define Hh   16
#define KVh  4
#define HDd  64
#define Ll   4
#define Ee   8
#define Ff   1024
#define Vv   32000

// ---------------- scratch (device globals; no allocation) ----------------
__device__ float g_x[Tt*Dd];
__device__ float g_h[Tt*Dd];
__device__ float g_q[Tt*Hh*HDd];
__device__ float g_k[Tt*KVh*HDd];
__device__ float g_v[Tt*KVh*HDd];
__device__ float g_scores[(size_t)Bz*Hh*Ss*Ss];   // 134 MB
__device__ float g_o[Tt*Hh*HDd];
__device__ float g_gbuf[(size_t)Ee*Tt*Ff];        // 67 MB per-expert gate
__device__ float g_ubuf[(size_t)Ee*Tt*Ff];        // 67 MB per-expert up
__device__ float g_dbuf[(size_t)Ee*Tt*Dd];        // 67 MB per-slot down output
__device__ int   g_eidx[Ee*Tt];
__device__ float g_egate[Ee*Tt];
__device__ int   g_ecnt[Ee];
__device__ int   g_slot[2*Tt];                    // token -> its two (e*Tt+pos) slots

// ---------------- helpers ----------------
__device__ __forceinline__ float tf32r(float x) {
    uint32_t u;
    asm("cvt.rna.tf32.f32 %0, %1;" : "=r"(u) : "f"(x));
    return __uint_as_float(u);
}

__device__ __forceinline__ void mma8(float* c, const uint32_t* a, const uint32_t* b) {
    asm volatile("mma.sync.aligned.m16n8k8.row.col.f32.tf32.tf32.f32 "
                 "{%0,%1,%2,%3}, {%4,%5,%6,%7}, {%8,%9}, {%0,%1,%2,%3};"
                 : "+f"(c[0]), "+f"(c[1]), "+f"(c[2]), "+f"(c[3])
                 : "r"(a[0]), "r"(a[1]), "r"(a[2]), "r"(a[3]),
                   "r"(b[0]), "r"(b[1]));
}

__device__ __forceinline__ float blockReduceSum256(float v) {
    __shared__ float sh[32];
    int lane = threadIdx.x & 31, wid = threadIdx.x >> 5;
    #pragma unroll
    for (int o = 16; o; o >>= 1) v += __shfl_xor_sync(0xffffffffu, v, o);
    if (lane == 0) sh[wid] = v;
    __syncthreads();
    int nw = (blockDim.x + 31) >> 5;
    float r = (threadIdx.x < nw) ? sh[threadIdx.x] : 0.f;
    if (wid == 0) {
        #pragma unroll
        for (int o = 16; o; o >>= 1) r += __shfl_xor_sync(0xffffffffu, r, o);
        if (lane == 0) sh[0] = r;
    }
    __syncthreads();
    float out = sh[0];
    __syncthreads();
    return out;
}

__device__ __forceinline__ float blockReduceMax256(float v) {
    __shared__ float sh[32];
    int lane = threadIdx.x & 31, wid = threadIdx.x >> 5;
    #pragma unroll
    for (int o = 16; o; o >>= 1) v = fmaxf(v, __shfl_xor_sync(0xffffffffu, v, o));
    if (lane == 0) sh[wid] = v;
    __syncthreads();
    int nw = (blockDim.x + 31) >> 5;
    float r = (threadIdx.x < nw) ? sh[threadIdx.x] : -INFINITY;
    if (wid == 0) {
        #pragma unroll
        for (int o = 16; o; o >>= 1) r = fmaxf(r, __shfl_xor_sync(0xffffffffu, r, o));
        if (lane == 0) sh[0] = r;
    }
    __syncthreads();
    float out = sh[0];
    __syncthreads();
    return out;
}

// ---------------- elementwise kernels ----------------
__global__ void embed_k(const int* __restrict__ tok, const float* __restrict__ emb,
                        float* __restrict__ x) {
    int i = blockIdx.x * 256 + threadIdx.x;
    int t = i / Dd, d = i % Dd;
    x[i] = emb[(long)tok[t] * Dd + d];
}

__global__ void rmsnorm_k(const float* __restrict__ x, const float* __restrict__ w,
                          float* __restrict__ out) {
    int row = blockIdx.x;
    const float* xr = x + (long)row * Dd;
    float* orow = out + (long)row * Dd;
    float ss = 0.f;
    #pragma unroll
    for (int i = 0; i < 4; i++) {
        float v = xr[threadIdx.x + i * 256];
        ss += v * v;
    }
    float tot = blockReduceSum256(ss);
    float scale = rsqrtf(tot / (float)Dd + 1e-6f);
    #pragma unroll
    for (int i = 0; i < 4; i++) {
        int d = threadIdx.x + i * 256;
        orow[d] = xr[d] * scale * w[d];
    }
}

// per-head RMSNorm + RoPE, in place. block = 64 threads = one (token, head)
__global__ void qknorm_rope_k(float* __restrict__ qk, const float* __restrict__ nw,
                              const int* __restrict__ pos, int nHeads, int ld) {
    int bid = blockIdx.x;
    int t = bid / nHeads, hh = bid % nHeads;
    float* v = qk + (long)t * ld + hh * HDd;
    int d = threadIdx.x;
    float x = v[d];
    float ss = x * x;
    #pragma unroll
    for (int o = 16; o; o >>= 1) ss += __shfl_xor_sync(0xffffffffu, ss, o);
    __shared__ float s2[2];
    if ((d & 31) == 0) s2[d >> 5] = ss;
    __syncthreads();
    float tot = s2[0] + s2[1];
    float scale = rsqrtf(tot / 64.f + 1e-6f);
    float xn = x * scale * nw[d];
    __shared__ float sh[64];
    sh[d] = xn;
    __syncthreads();
    int p = pos[t];
    int fi = d & 31;
    float inv = powf(1e6f, -(float)fi / 32.f);
    float ang = (float)p * inv;
    float c = cosf(ang), s = sinf(ang);
    float other = (d < 32) ? sh[d + 32] : sh[d - 32];
    float rot = (d < 32) ? -other : other;
    v[d] = xn * c + rot * s;
}

// causal softmax; zero-fills only (q, bandEnd) — P.V's trapezoid-K never reads past it
__global__ void softmax_k(float* __restrict__ scores) {
    long row = blockIdx.x;                 // B*H*S rows
    int q = (int)(row % Ss);
    float* p = scores + row * Ss;
    int valid = q + 1;
    float mx = -INFINITY;
    for (int j = threadIdx.x; j < valid; j += 256) mx = fmaxf(mx, p[j]);
    mx = blockReduceMax256(mx);
    float sum = 0.f;
    for (int j = threadIdx.x; j < valid; j += 256) {
        float e = expf(p[j] - mx);
        p[j] = e;
        sum += e;
    }
    sum = blockReduceSum256(sum);
    float inv = 1.f / sum;
    for (int j = threadIdx.x; j < valid; j += 256) p[j] *= inv;
    int bandEnd = ((q >> 6) + 1) << 6;
    for (int j = valid + threadIdx.x; j < bandEnd; j += 256) p[j] = 0.f;
}

__global__ void zero_cnt_k(int* c) { if (threadIdx.x < Ee) c[threadIdx.x] = 0; }

// router: logits = h @ rw [D,E]; top-2; normalize; fill expert lists + token slots
__global__ void router_k(const float* __restrict__ h, const float* __restrict__ rw,
                         int* __restrict__ ecnt, int* __restrict__ eidx,
                         float* __restrict__ egate, int* __restrict__ slot) {
    int t = blockIdx.x;
    int lane = threadIdx.x & 31, w = threadIdx.x >> 5;   // warp per expert
    const float* hr = h + (long)t * Dd;
    float s = 0.f;
    for (int d = lane; d < Dd; d += 32) s += hr[d] * rw[(long)d * Ee + w];
    #pragma unroll
    for (int o = 16; o; o >>= 1) s += __shfl_xor_sync(0xffffffffu, s, o);
    __shared__ float lg[Ee];
    if (lane == 0) lg[w] = s;
    __syncthreads();
    if (threadIdx.x == 0) {
        int a = 0;
        #pragma unroll
        for (int i = 1; i < Ee; i++) if (lg[i] > lg[a]) a = i;
        int b = (a == 0) ? 1 : 0;
        #pragma unroll
        for (int i = 0; i < Ee; i++) if (i != a && lg[i] > lg[b]) b = i;
        float wa = 1.f / (1.f + expf(lg[b] - lg[a]));
        float wb = 1.f - wa;
        int pa = atomicAdd(&ecnt[a], 1);
        eidx[a * Tt + pa] = t; egate[a * Tt + pa] = wa;
        int pb = atomicAdd(&ecnt[b], 1);
        eidx[b * Tt + pb] = t; egate[b * Tt + pb] = wb;
        slot[2 * t + 0] = a * Tt + pa;
        slot[2 * t + 1] = b * Tt + pb;
    }
}

// compacted silu*up: exactly 2*Tt active rows across experts (sum(cnt) == 2*Tt);
// flat row r mapped to (expert, local row) via an 8-step prefix over cnt.
__global__ void silu_compact_k(float* __restrict__ g, const float* __restrict__ u,
                               const int* __restrict__ cnt) {
    long i = (long)blockIdx.x * 256 + threadIdx.x;   // [0, 2*Tt*Ff)
    int r = (int)(i / Ff), col = (int)(i % Ff);
    int e = -1, lr = 0, acc = 0;
    #pragma unroll
    for (int j = 0; j < Ee; j++) {
        int c = cnt[j];
        if (e < 0 && r < acc + c) { e = j; lr = r - acc; }
        acc += c;
    }
    if (e < 0) return;
    long idx = (long)e * ((long)Tt * Ff) + (long)lr * Ff + col;
    float x = g[idx];
    g[idx] = (x / (1.f + expf(-x))) * u[idx];
}

// deterministic combine: x[t] += gate0*dbuf[slot0] + gate1*dbuf[slot1]
__global__ void combine_k(float* __restrict__ x, const float* __restrict__ dbuf,
                          const int* __restrict__ slot, const float* __restrict__ eg) {
    long i = (long)blockIdx.x * 256 + threadIdx.x;   // Tt*Dd
    int t = (int)(i / Dd), d = (int)(i % Dd);
    int s0 = slot[2 * t], s1 = slot[2 * t + 1];
    x[i] += eg[s0] * dbuf[(long)s0 * Dd + d] + eg[s1] * dbuf[(long)s1 * Dd + d];
}

// ========== MODE semantics (both GEMM kernels) ==========
// MODE 0: batched heads via z (b=z/nH, h=z%nH; strides sAb/sAh/...)
// MODE 1: dual output; z=0 -> (B,C), z=1 -> (B2,C2)
// MODE 2: expert dual + gather: z -> (e=z>>1, which=z&1); M=Mdev[e];
//         A row m -> A[idx[m]]; B/C from (which? B2/C2 : B/C) + e*stride
// MODE 3: expert single: z=e; M=Mdev[e]; A/B/C += e*stride
// MODE 4 (gemm64 only): triple output Q/K/V; z=0 -> (B,C,N), z=1 -> (B2,C2,KV),
//         z=2 -> (B3,C3,KV)
// kTrap (gemm64 only): bound K-loop at m0+64 (P.V trapezoid over causal scores)
// NOTE: no default args on __global__ functions (CUDA restriction) — all call
//       sites pass the full argument list explicitly.

// ---------------- 3xTF32 GEMM, 64x64 tile (small/batched shapes) ----------------
// 128 threads = 4 warps (2x2), warp tile 32x32. Raw fp32 smem; hi/lo split at
// fragment load (halves LDS traffic vs hi/lo-in-smem). N%64==0, K%16==0.
template<int MODE, bool TRANSB>
__global__ void __launch_bounds__(128) gemm64_k(
    const float* __restrict__ A, const float* __restrict__ B,
    const float* __restrict__ B2, float* __restrict__ C, float* __restrict__ C2,
    int M, int N, int K, int lda, int ldb, int ldc,
    float alpha, int addC, int causal,
    const int* __restrict__ idxBase, const int* __restrict__ MdevBase,
    long sAb, long sAh, long sBb, long sBh, long sCb, long sCh,
    int nH, int hDiv, long eA, long eB, long eC,
    const float* __restrict__ B3, float* __restrict__ C3, int kTrap)
{
    const int* idx = nullptr;
    if (MODE == 0) {
        int z = blockIdx.z;
        int b = z / nH, h = z % nH;
        A += (long)b * sAb + (long)h * sAh;
        B += (long)b * sBb + (long)(h / hDiv) * sBh;
        C += (long)b * sCb + (long)h * sCh;
    } else if (MODE == 1) {
        if (blockIdx.z) { B = B2; C = C2; }
    } else if (MODE == 2) {
        int e = blockIdx.z >> 1, which = blockIdx.z & 1;
        M = MdevBase[e];
        idx = idxBase + e * Tt;
        B = (which ? B2 : B) + (long)e * eB;
        C = (which ? C2 : C) + (long)e * eC;
    } else if (MODE == 3) {
        int e = blockIdx.z;
        M = MdevBase[e];
        A += (long)e * eA;
        B += (long)e * eB;
        C += (long)e * eC;
    } else if (MODE == 4) {
        int z = blockIdx.z;
        if (z == 1) { B = B2; C = C2; N = KVh * HDd; ldb = KVh * HDd; ldc = KVh * HDd; }
        else if (z == 2) { B = B3; C = C3; N = KVh * HDd; ldb = KVh * HDd; ldc = KVh * HDd; }
    }
    constexpr bool GATHER = (MODE == 2);

    int m0 = blockIdx.y * 64, n0 = blockIdx.x * 64;
    if (m0 >= M || n0 >= N) return;
    if (causal && n0 >= m0 + 64) return;

    __shared__ float As[2][64][20];   // raw fp32; stride 20 conflict-free
    __shared__ float Bs[2][16][72];   // raw fp32; stride 72 conflict-free

    int tid = threadIdx.x;
    int lane = tid & 31, warp = tid >> 5;
    int wm = (warp >> 1) * 32, wn = (warp & 1) * 32;
    int qrow = lane >> 2, qk = lane & 3;

    int ar_r = tid >> 2;               // 0..31
    int ac4 = (tid & 3) * 4;
    int gr0 = m0 + ar_r, gr1 = gr0 + 32;
    bool av0 = gr0 < M, av1 = gr1 < M;
    long arow0 = 0, arow1 = 0;
    if (av0) arow0 = (long)(GATHER ? idx[gr0] : gr0) * lda;
    if (av1) arow1 = (long)(GATHER ? idx[gr1] : gr1) * lda;

    int bnr, bc4;
    if (TRANSB) { bnr = tid >> 2; bc4 = (tid & 3) * 4; }
    else        { bnr = tid >> 4; bc4 = (tid & 15) * 4; }

    float4 pa0, pa1, pb0, pb1;
    const float4 z4 = make_float4(0.f, 0.f, 0.f, 0.f);

    float acc[2][4][4];
    #pragma unroll
    for (int mt = 0; mt < 2; mt++)
        #pragma unroll
        for (int nt = 0; nt < 4; nt++)
            #pragma unroll
            for (int i = 0; i < 4; i++) acc[mt][nt][i] = 0.f;

    auto LDG = [&](int k0) {
        pa0 = av0 ? *(const float4*)(A + arow0 + k0 + ac4) : z4;
        pa1 = av1 ? *(const float4*)(A + arow1 + k0 + ac4) : z4;
        if (TRANSB) {
            pb0 = *(const float4*)(B + (long)(n0 + bnr) * ldb + k0 + bc4);
            pb1 = *(const float4*)(B + (long)(n0 + bnr + 32) * ldb + k0 + bc4);
        } else {
            pb0 = *(const float4*)(B + (long)(k0 + bnr) * ldb + n0 + bc4);
            pb1 = *(const float4*)(B + (long)(k0 + bnr + 8) * ldb + n0 + bc4);
        }
    };

    auto STS = [&](int buf) {
        *(float4*)&As[buf][ar_r][ac4] = pa0;
        *(float4*)&As[buf][ar_r + 32][ac4] = pa1;
        if (TRANSB) {
            Bs[buf][bc4 + 0][bnr] = pb0.x;
            Bs[buf][bc4 + 1][bnr] = pb0.y;
            Bs[buf][bc4 + 2][bnr] = pb0.z;
            Bs[buf][bc4 + 3][bnr] = pb0.w;
            Bs[buf][bc4 + 0][bnr + 32] = pb1.x;
            Bs[buf][bc4 + 1][bnr + 32] = pb1.y;
            Bs[buf][bc4 + 2][bnr + 32] = pb1.z;
            Bs[buf][bc4 + 3][bnr + 32] = pb1.w;
        } else {
            *(float4*)&Bs[buf][bnr][bc4] = pb0;
            *(float4*)&Bs[buf][bnr + 8][bc4] = pb1;
        }
    };

    auto split = [&](float v, uint32_t& hi, uint32_t& lo) {
        float h = tf32r(v);
        hi = __float_as_uint(h);
        lo = __float_as_uint(tf32r(v - h));
    };

    auto COMPUTE = [&](int buf) {
        #pragma unroll
        for (int ks = 0; ks < 2; ks++) {
            int kk = ks * 8 + qk;
            uint32_t afh[2][4], afl[2][4];
            #pragma unroll
            for (int mt = 0; mt < 2; mt++) {
                int r = wm + mt * 16 + qrow;
                split(As[buf][r][kk],          afh[mt][0], afl[mt][0]);
                split(As[buf][r + 8][kk],      afh[mt][1], afl[mt][1]);
                split(As[buf][r][kk + 4],      afh[mt][2], afl[mt][2]);
                split(As[buf][r + 8][kk + 4],  afh[mt][3], afl[mt][3]);
            }
            uint32_t bfh[4][2], bfl[4][2];
            #pragma unroll
            for (int nt = 0; nt < 4; nt++) {
                int cn = wn + nt * 8 + qrow;
                split(Bs[buf][kk][cn],      bfh[nt][0], bfl[nt][0]);
                split(Bs[buf][kk + 4][cn],  bfh[nt][1], bfl[nt][1]);
            }
            #pragma unroll
            for (int mt = 0; mt < 2; mt++)
                #pragma unroll
                for (int nt = 0; nt < 4; nt++) {
                    mma8(acc[mt][nt], afh[mt], bfl[nt]);
                    mma8(acc[mt][nt], afl[mt], bfh[nt]);
                    mma8(acc[mt][nt], afh[mt], bfh[nt]);
                }
        }
    };

    int KT = K >> 4;
    if (kTrap) {
        int kt2 = (m0 + 64) >> 4;
        if (kt2 < KT) KT = kt2;
    }
    LDG(0);
    STS(0);
    __syncthreads();
    for (int kt = 0; kt < KT; kt++) {
        int cur = kt & 1;
        bool more = (kt + 1) < KT;
        if (more) LDG((kt + 1) * 16);
        COMPUTE(cur);
        if (more) {
            __syncthreads();
            STS(cur ^ 1);
            __syncthreads();
        }
    }

    #pragma unroll
    for (int mt = 0; mt < 2; mt++) {
        #pragma unroll
        for (int half = 0; half < 2; half++) {
            int m = m0 + wm + mt * 16 + qrow + half * 8;
            if (m >= M) continue;
            long crow = (long)m * ldc;
            #pragma unroll
            for (int nt = 0; nt < 4; nt++) {
                int col = n0 + wn + nt * 8 + 2 * qk;
                float v0 = alpha * acc[mt][nt][half * 2 + 0];
                float v1 = alpha * acc[mt][nt][half * 2 + 1];
                float2* cp = (float2*)(C + crow + col);
                if (addC) {
                    float2 old = *cp;
                    old.x += v0; old.y += v1;
                    *cp = old;
                } else {
                    *cp = make_float2(v0, v1);
                }
            }
        }
    }
}

// ---------------- 3xTF32 GEMM, 128x128 tile (large shapes) ----------------
// 256 threads = 8 warps (2x4), warp tile 64x32. Raw fp32 smem; hi/lo split at
// fragment load. launch_bounds(256,2): 128-reg budget -> 2 blocks/SM.
template<int MODE, bool TRANSB>
__global__ void __launch_bounds__(256, 2) gemm128_k(
    const float* __restrict__ A, const float* __restrict__ B,
    const float* __restrict__ B2, float* __restrict__ C, float* __restrict__ C2,
    int M, int N, int K, int lda, int ldb, int ldc,
    float alpha, int addC, int causal,
    const int* __restrict__ idxBase, const int* __restrict__ MdevBase,
    long sAb, long sAh, long sBb, long sBh, long sCb, long sCh,
    int nH, int hDiv, long eA, long eB, long eC)
{
    const int* idx = nullptr;
    if (MODE == 0) {
        int z = blockIdx.z;
        int b = z / nH, h = z % nH;
        A += (long)b * sAb + (long)h * sAh;
        B += (long)b * sBb + (long)(h / hDiv) * sBh;
        C += (long)b * sCb + (long)h * sCh;
    } else if (MODE == 1) {
        if (blockIdx.z) { B = B2; C = C2; }
    } else if (MODE == 2) {
        int e = blockIdx.z >> 1, which = blockIdx.z & 1;
        M = MdevBase[e];
        idx = idxBase + e * Tt;
        B = (which ? B2 : B) + (long)e * eB;
        C = (which ? C2 : C) + (long)e * eC;
    } else if (MODE == 3) {
        int e = blockIdx.z;
        M = MdevBase[e];
        A += (long)e * eA;
        B += (long)e * eB;
        C += (long)e * eC;
    }
    constexpr bool GATHER = (MODE == 2);

    int m0 = blockIdx.y * 128, n0 = blockIdx.x * 128;
    if (m0 >= M) return;
    if (causal && n0 >= m0 + 128) return;

    __shared__ float As[2][128][20];   // stride 20: conflict-free frag reads
    __shared__ float Bs[2][16][136];   // stride 136 (=8 mod 32): conflict-free

    int tid = threadIdx.x;
    int lane = tid & 31, warp = tid >> 5;
    int wm = (warp >> 2) * 64, wn = (warp & 3) * 32;
    int qrow = lane >> 2, qk = lane & 3;

    int ar_r = tid >> 2;               // 0..63
    int ac4 = (tid & 3) * 4;
    int gr0 = m0 + ar_r, gr1 = gr0 + 64;
    bool av0 = gr0 < M, av1 = gr1 < M;
    long arow0 = 0, arow1 = 0;
    if (av0) arow0 = (long)(GATHER ? idx[gr0] : gr0) * lda;
    if (av1) arow1 = (long)(GATHER ? idx[gr1] : gr1) * lda;

    int bnr, bc4;
    bool bv0, bv1;
    if (TRANSB) {
        bnr = tid >> 2; bc4 = (tid & 3) * 4;       // n-rows bnr, bnr+64
        bv0 = (n0 + bnr) < N; bv1 = (n0 + bnr + 64) < N;
    } else {
        bnr = tid >> 5; bc4 = (tid & 31) * 4;      // k-rows bnr, bnr+8
        bv0 = bv1 = (n0 + bc4) < N;
    }

    float4 pa0, pa1, pb0, pb1;
    const float4 z4 = make_float4(0.f, 0.f, 0.f, 0.f);

    float acc[4][4][4];
    #pragma unroll
    for (int mt = 0; mt < 4; mt++)
        #pragma unroll
        for (int nt = 0; nt < 4; nt++)
            #pragma unroll
            for (int i = 0; i < 4; i++) acc[mt][nt][i] = 0.f;

    auto LDG = [&](int k0) {
        pa0 = av0 ? *(const float4*)(A + arow0 + k0 + ac4) : z4;
        pa1 = av1 ? *(const float4*)(A + arow1 + k0 + ac4) : z4;
        if (TRANSB) {
            pb0 = bv0 ? *(const float4*)(B + (long)(n0 + bnr) * ldb + k0 + bc4) : z4;
            pb1 = bv1 ? *(const float4*)(B + (long)(n0 + bnr + 64) * ldb + k0 + bc4) : z4;
        } else {
            pb0 = bv0 ? *(const float4*)(B + (long)(k0 + bnr) * ldb + n0 + bc4) : z4;
            pb1 = bv1 ? *(const float4*)(B + (long)(k0 + bnr + 8) * ldb + n0 + bc4) : z4;
        }
    };

    auto STS = [&](int buf) {
        *(float4*)&As[buf][ar_r][ac4] = pa0;
        *(float4*)&As[buf][ar_r + 64][ac4] = pa1;
        if (TRANSB) {
            Bs[buf][bc4 + 0][bnr] = pb0.x;
            Bs[buf][bc4 + 1][bnr] = pb0.y;
            Bs[buf][bc4 + 2][bnr] = pb0.z;
            Bs[buf][bc4 + 3][bnr] = pb0.w;
            Bs[buf][bc4 + 0][bnr + 64] = pb1.x;
            Bs[buf][bc4 + 1][bnr + 64] = pb1.y;
            Bs[buf][bc4 + 2][bnr + 64] = pb1.z;
            Bs[buf][bc4 + 3][bnr + 64] = pb1.w;
        } else {
            *(float4*)&Bs[buf][bnr][bc4] = pb0;
            *(float4*)&Bs[buf][bnr + 8][bc4] = pb1;
        }
    };

    auto split = [&](float v, uint32_t& hi, uint32_t& lo) {
        float h = tf32r(v);
        hi = __float_as_uint(h);
        lo = __float_as_uint(tf32r(v - h));
    };

    auto COMPUTE = [&](int buf) {
        #pragma unroll
        for (int ks = 0; ks < 2; ks++) {
            int kk = ks * 8 + qk;
            uint32_t afh[4][4], afl[4][4];
            #pragma unroll
            for (int mt = 0; mt < 4; mt++) {
                int r = wm + mt * 16 + qrow;
                split(As[buf][r][kk],          afh[mt][0], afl[mt][0]);
                split(As[buf][r + 8][kk],      afh[mt][1], afl[mt][1]);
                split(As[buf][r][kk + 4],      afh[mt][2], afl[mt][2]);
                split(As[buf][r + 8][kk + 4],  afh[mt][3], afl[mt][3]);
            }
            uint32_t bfh[4][2], bfl[4][2];
            #pragma unroll
            for (int nt = 0; nt < 4; nt++) {
                int cn = wn + nt * 8 + qrow;
                split(Bs[buf][kk][cn],      bfh[nt][0], bfl[nt][0]);
                split(Bs[buf][kk + 4][cn],  bfh[nt][1], bfl[nt][1]);
            }
            #pragma unroll
            for (int mt = 0; mt < 4; mt++)
                #pragma unroll
                for (int nt = 0; nt < 4; nt++) {
                    mma8(acc[mt][nt], afh[mt], bfl[nt]);
                    mma8(acc[mt][nt], afl[mt], bfh[nt]);
                    mma8(acc[mt][nt], afh[mt], bfh[nt]);
                }
        }
    };

    int KT = K >> 4;
    LDG(0);
    STS(0);
    __syncthreads();
    for (int kt = 0; kt < KT; kt++) {
        int cur = kt & 1;
        bool more = (kt + 1) < KT;
        if (more) LDG((kt + 1) * 16);
        COMPUTE(cur);
        if (more) {
            __syncthreads();
            STS(cur ^ 1);
            __syncthreads();
        }
    }

    #pragma unroll
    for (int mt = 0; mt < 4; mt++) {
        #pragma unroll
        for (int half = 0; half < 2; half++) {
            int m = m0 + wm + mt * 16 + qrow + half * 8;
            if (m >= M) continue;
            long crow = (long)m * ldc;
            #pragma unroll
            for (int nt = 0; nt < 4; nt++) {
                int colg = n0 + wn + nt * 8;
                if (colg >= N) continue;
                int col = colg + 2 * qk;
                float v0 = alpha * acc[mt][nt][half * 2 + 0];
                float v1 = alpha * acc[mt][nt][half * 2 + 1];
                float2* cp = (float2*)(C + crow + col);
                if (addC) {
                    float2 old = *cp;
                    old.x += v0; old.y += v1;
                    *cp = old;
                } else {
                    *cp = make_float2(v0, v1);
                }
            }
        }
    }
}

// ---------------- host side ----------------
extern "C" void kernel_launch(void* const* d_in, const int* in_sizes, int n_in,
                              void* d_out, int out_size) {
    const int*   tok    = (const int*)d_in[0];
    const int*   pos    = (const int*)d_in[1];
    const float* emb    = (const float*)d_in[2];
    const float* attnw  = (const float*)d_in[3];
    const float* wq     = (const float*)d_in[4];
    const float* wk     = (const float*)d_in[5];
    const float* wv     = (const float*)d_in[6];
    const float* qnw    = (const float*)d_in[7];
    const float* knw    = (const float*)d_in[8];
    const float* wo     = (const float*)d_in[9];
    const float* ffnw   = (const float*)d_in[10];
    const float* rw     = (const float*)d_in[11];
    const float* gw     = (const float*)d_in[12];
    const float* uw     = (const float*)d_in[13];
    const float* dw     = (const float*)d_in[14];
    const float* fnw    = (const float*)d_in[15];
    float* out = (float*)d_out;

    float *px, *ph, *pq, *pk, *pv, *po, *pscores, *pgbuf, *pubuf, *pdbuf, *pegate;
    int *peidx, *pecnt, *pslot;
    cudaGetSymbolAddress((void**)&px, g_x);
    cudaGetSymbolAddress((void**)&ph, g_h);
    cudaGetSymbolAddress((void**)&pq, g_q);
    cudaGetSymbolAddress((void**)&pk, g_k);
    cudaGetSymbolAddress((void**)&pv, g_v);
    cudaGetSymbolAddress((void**)&po, g_o);
    cudaGetSymbolAddress((void**)&pscores, g_scores);
    cudaGetSymbolAddress((void**)&pgbuf, g_gbuf);
    cudaGetSymbolAddress((void**)&pubuf, g_ubuf);
    cudaGetSymbolAddress((void**)&pdbuf, g_dbuf);
    cudaGetSymbolAddress((void**)&pegate, g_egate);
    cudaGetSymbolAddress((void**)&peidx, g_eidx);
    cudaGetSymbolAddress((void**)&pecnt, g_ecnt);
    cudaGetSymbolAddress((void**)&pslot, g_slot);

    const long ZL = 0;

    // embed
    embed_k<<<(Tt * Dd) / 256, 256>>>(tok, emb, px);

    for (int l = 0; l < Ll; l++) {
        const float* wq_l = wq + (long)l * Dd * (Hh * HDd);
        const float* wk_l = wk + (long)l * Dd * (KVh * HDd);
        const float* wv_l = wv + (long)l * Dd * (KVh * HDd);
        const float* wo_l = wo + (long)l * (Hh * HDd) * Dd;
        const float* gw_l = gw + (long)l * Ee * Dd * Ff;
        const float* uw_l = uw + (long)l * Ee * Dd * Ff;
        const float* dw_l = dw + (long)l * Ee * Ff * Dd;

        // ---- attention ----
        rmsnorm_k<<<Tt, 256>>>(px, attnw + (long)l * Dd, ph);

        // Q + K + V fused in ONE launch (MODE 4: z=0 Q, z=1 K, z=2 V)
        gemm64_k<4,false><<<dim3(16, 32, 3), 128>>>(
            ph, wq_l, wk_l, pq, pk,
            Tt, Hh * HDd, Dd, Dd, Hh * HDd, Hh * HDd,
            1.f, 0, 0, nullptr, nullptr,
            ZL, ZL, ZL, ZL, ZL, ZL, 1, 1, ZL, ZL, ZL,
            wv_l, pv, 0);

        qknorm_rope_k<<<Tt * Hh, 64>>>(pq, qnw + (long)l * HDd, pos, Hh, Hh * HDd);
        qknorm_rope_k<<<Tt * KVh, 64>>>(pk, knw + (long)l * HDd, pos, KVh, KVh * HDd);

        // scores = Q @ K^T * scale (128-tile, batched, causal skip)
        gemm128_k<0,true><<<dim3(8, 8, Bz * Hh), 256>>>(
            pq, pk, nullptr, pscores, nullptr,
            Ss, Ss, HDd, Hh * HDd, KVh * HDd, Ss,
            0.125f, 0, 1, nullptr, nullptr,
            (long)Ss * Hh * HDd, (long)HDd,
            (long)Ss * KVh * HDd, (long)HDd,
            (long)Hh * Ss * Ss, (long)Ss * Ss,
            Hh, Hh / KVh, ZL, ZL, ZL);

        softmax_k<<<Bz * Hh * Ss, 256>>>(pscores);

        // O = P @ V (64-tile, trapezoid-K: K loop bounded at m0+64)
        gemm64_k<0,false><<<dim3(1, 16, Bz * Hh), 128>>>(
            pscores, pv, nullptr, po, nullptr,
            Ss, HDd, Ss, Ss, KVh * HDd, Hh * HDd,
            1.f, 0, 0, nullptr, nullptr,
            (long)Hh * Ss * Ss, (long)Ss * Ss,
            (long)Ss * KVh * HDd, (long)HDd,
            (long)Ss * Hh * HDd, (long)HDd,
            Hh, Hh / KVh, ZL, ZL, ZL,
            nullptr, nullptr, 1);

        // x += O @ wo (64-tile: grid 512)
        gemm64_k<0,false><<<dim3(16, 32, 1), 128>>>(
            po, wo_l, nullptr, px, nullptr,
            Tt, Dd, Hh * HDd, Hh * HDd, Dd, Dd,
            1.f, 1, 0, nullptr, nullptr,
            ZL, ZL, ZL, ZL, ZL, ZL, 1, 1, ZL, ZL, ZL,
            nullptr, nullptr, 0);

        // ---- MoE ----
        rmsnorm_k<<<Tt, 256>>>(px, ffnw + (long)l * Dd, ph);
        zero_cnt_k<<<1, 32>>>(pecnt);
        router_k<<<Tt, 256>>>(ph, rw + (long)l * Dd * Ee, pecnt, peidx, pegate, pslot);

        // all experts' gate+up in ONE launch (128-tile): z = e*2 + which
        gemm128_k<2,false><<<dim3(8, 16, 2 * Ee), 256>>>(
            ph, gw_l, uw_l, pgbuf, pubuf,
            Tt, Ff, Dd, Dd, Ff, Ff,
            1.f, 0, 0, peidx, pecnt,
            ZL, ZL, ZL, ZL, ZL, ZL, 1, 1,
            ZL, (long)Dd * Ff, (long)Tt * Ff);

        // compacted silu*up over exactly the 2*Tt active rows
        silu_compact_k<<<(int)(((long)2 * Tt * Ff) / 256), 256>>>(pgbuf, pubuf, pecnt);

        // all experts' down-proj in ONE launch (128-tile) -> per-slot buffer
        gemm128_k<3,false><<<dim3(8, 16, Ee), 256>>>(
            pgbuf, dw_l, nullptr, pdbuf, nullptr,
            Tt, Dd, Ff, Ff, Dd, Dd,
            1.f, 0, 0, nullptr, pecnt,
            ZL, ZL, ZL, ZL, ZL, ZL, 1, 1,
            (long)Tt * Ff, (long)Ff * Dd, (long)Tt * Dd);

        // deterministic combine: x += gate0*y0 + gate1*y1
        combine_k<<<(Tt * Dd) / 256, 256>>>(px, pdbuf, pslot, pegate);
    }

    // final norm + tied lm_head (128-tile: grid 250x16 = 4000)
    rmsnorm_k<<<Tt, 256>>>(px, fnw, ph);
    gemm128_k<0,true><<<dim3(Vv / 128, Tt / 128, 1), 256>>>(
        ph, emb, nullptr, out, nullptr,
        Tt, Vv, Dd, Dd, Dd, Vv,
        1.f, 0, 0, nullptr, nullptr,
        ZL, ZL, ZL, ZL, ZL, ZL, 1, 1, ZL, ZL, ZL);
}